// round 7
// baseline (speedup 1.0000x reference)
#include <cuda_runtime.h>
#include <cuda_bf16.h>
typedef unsigned int u32; typedef unsigned long long u64;

#define NT1 128
#define ED  256
#define HD  512
#define G4  2048
#define RTOT 2176
#define NCT 250
#define VV  32000

__device__ float d_xT[ED*NT1];
__device__ float d_xg[2*NT1*G4];
__device__ float d_hbuf[2*2*HD];
__device__ float d_hcat[NT1*2*HD];
__device__ float d_u[NT1*HD];
__device__ float d_s[NT1*HD];
__device__ __align__(16) __nv_bfloat16 d_zb[(size_t)RTOT*HD];
__device__ __align__(16) __nv_bfloat16 d_fWb[(size_t)VV*HD];
__device__ __align__(16) __nv_bfloat16 d_gWb[(size_t)VV*HD];
__device__ float d_pm[(size_t)RTOT*NCT];
__device__ float d_ps[(size_t)RTOT*NCT];
__device__ float d_tgt[RTOT];
__device__ u32 d_keys[4];
__device__ int d_barf[128];
__device__ float d_kl, d_acc;

__device__ __forceinline__ uint2 tf2x32(u32 k0,u32 k1,u32 c0,u32 c1){
    u32 ks2=0x1BD11BDAu^k0^k1, x0=c0+k0, x1=c1+k1;
#define TFR(r) {x0+=x1; x1=__funnelshift_l(x1,x1,r); x1^=x0;}
    TFR(13)TFR(15)TFR(26)TFR(6)  x0+=k1;  x1+=ks2+1u;
    TFR(17)TFR(29)TFR(16)TFR(24) x0+=ks2; x1+=k0+2u;
    TFR(13)TFR(15)TFR(26)TFR(6)  x0+=k0;  x1+=k1+3u;
    TFR(17)TFR(29)TFR(16)TFR(24) x0+=k1;  x1+=ks2+4u;
    TFR(13)TFR(15)TFR(26)TFR(6)  x0+=ks2; x1+=k0+5u;
#undef TFR
    return make_uint2(x0,x1);
}
__device__ __forceinline__ float jnormal(u32 bits){
    float f=__uint_as_float((bits>>9)|0x3f800000u)-1.0f;
    const float lo=__int_as_float(0xBF7FFFFF);
    float u=fmaxf(lo, f*(1.0f-lo)+lo);
    float w=-log1pf(-u*u), p;
    if(w<5.0f){ w-=2.5f;
        p=2.81022636e-08f;           p=fmaf(p,w,3.43273939e-07f);
        p=fmaf(p,w,-3.5233877e-06f); p=fmaf(p,w,-4.39150654e-06f);
        p=fmaf(p,w,0.00021858087f);  p=fmaf(p,w,-0.00125372503f);
        p=fmaf(p,w,-0.00417768164f); p=fmaf(p,w,0.246640727f);
        p=fmaf(p,w,1.50140941f);
    } else { w=sqrtf(w)-3.0f;
        p=-0.000200214257f;          p=fmaf(p,w,0.000100950558f);
        p=fmaf(p,w,0.00134934322f);  p=fmaf(p,w,-0.00367342844f);
        p=fmaf(p,w,0.00573950773f);  p=fmaf(p,w,-0.0076224613f);
        p=fmaf(p,w,0.00943887047f);  p=fmaf(p,w,1.00167406f);
        p=fmaf(p,w,2.83297682f);
    }
    return 1.41421354f*(p*u);
}
__device__ __forceinline__ float sigf(float x){ return 1.0f/(1.0f+expf(-x)); }
__device__ __forceinline__ float fsig(float x){ return __fdividef(1.0f,1.0f+__expf(-x)); }
__device__ __forceinline__ float ftanh(float x){ return 1.0f-__fdividef(2.0f,__expf(2.0f*x)+1.0f); }
__device__ __forceinline__ void st_rel(int* p,int v){
    asm volatile("st.release.gpu.global.b32 [%0], %1;"::"l"(p),"r"(v):"memory");
}
__device__ __forceinline__ int ld_acq(const int* p){
    int v; asm volatile("ld.acquire.gpu.global.b32 %0, [%1];":"=r"(v):"l"(p):"memory"); return v;
}

__global__ void k_init(const int* __restrict__ wl1, const float* __restrict__ emb){
    int tid=blockIdx.x*blockDim.x+threadIdx.x;
    int t=tid&127, k=tid>>7;
    d_xT[k*NT1+t]=emb[(size_t)wl1[t]*ED+k];
    if(tid<2048) d_hbuf[tid]=0.0f;
    if(tid<128) d_barf[tid]=0;
    if(tid==0){
        d_kl=0.0f; d_acc=0.0f;
        uint2 a=tf2x32(0u,42u,0u,0u), b=tf2x32(0u,42u,0u,1u);
        d_keys[0]=a.x; d_keys[1]=a.y; d_keys[2]=b.x; d_keys[3]=b.y;
    }
}

__global__ void k_cvt(const float* __restrict__ fW,const float* __restrict__ gW){
    size_t i=((size_t)blockIdx.x*blockDim.x+threadIdx.x)*4;
    float4 a=*(const float4*)(fW+i);
    __nv_bfloat162* o=(__nv_bfloat162*)(d_fWb+i);
    o[0]=__floats2bfloat162_rn(a.x,a.y); o[1]=__floats2bfloat162_rn(a.z,a.w);
    float4 b=*(const float4*)(gW+i);
    __nv_bfloat162* o2=(__nv_bfloat162*)(d_gWb+i);
    o2[0]=__floats2bfloat162_rn(b.x,b.y); o2[1]=__floats2bfloat162_rn(b.z,b.w);
}

__global__ void k_xg(const float* __restrict__ Wf,const float* __restrict__ bif,
                     const float* __restrict__ bhf,const float* __restrict__ Wb,
                     const float* __restrict__ bib,const float* __restrict__ bhb){
    int dir=blockIdx.y, j0=blockIdx.x*16, t=threadIdx.x;
    const float* W = dir?Wb:Wf; const float* b1=dir?bib:bif; const float* b2=dir?bhb:bhf;
    __shared__ float Ws[16][ED]; __shared__ float bs[16];
    for(int i=t;i<16*ED;i+=128) Ws[i>>8][i&255]=W[(size_t)(j0+(i>>8))*ED+(i&255)];
    if(t<16) bs[t]=b1[j0+t]+b2[j0+t];
    __syncthreads();
    int ts = dir?(127-t):t;
    float acc[16];
#pragma unroll
    for(int c=0;c<16;c++) acc[c]=0.0f;
    for(int k=0;k<ED;k++){
        float xv=d_xT[k*NT1+ts];
#pragma unroll
        for(int c=0;c<16;c++) acc[c]=fmaf(xv,Ws[c][k],acc[c]);
    }
#pragma unroll
    for(int c=0;c<16;c++) d_xg[(size_t)(dir*NT1+t)*G4+j0+c]=acc[c]+bs[c];
}

// persistent bi-LSTM: 32 blocks/dir x 512 thr, 16 h-units/block (1/warp), Whh in regs.
// Step sync: per-block release flag (distinct addresses) + single-warp uniform acquire poll.
__global__ void __launch_bounds__(512,1) k_lstm(const float* __restrict__ Whf,
                                                const float* __restrict__ Whb){
    int bid=blockIdx.x, dir=bid>>5, blk=bid&31, j0=blk*16;
    int tid=threadIdx.x, wp=tid>>5, l=tid&31, g=l>>3, seg=l&7;
    int j=j0+wp;
    const float* Whh = dir?Whb:Whf;
    float w[64];
    {
        const float* wr=Whh+(size_t)(g*HD+j)*HD+seg;
#pragma unroll
        for(int ii=0;ii<64;ii++) w[ii]=wr[ii*8];
    }
    __shared__ float hs[HD];
    __shared__ float xgs[NT1*64];
    for(int idx=tid; idx<NT1*64; idx+=512){
        int s=idx>>6, r=idx&63, gg=r>>4, uu=r&15;
        xgs[idx]=d_xg[(size_t)(dir*NT1+s)*G4 + gg*HD + j0+uu];
    }
    float c=0.0f;
    int* flags=&d_barf[dir*32];
    __syncthreads();
    for(int s=0;s<NT1;s++){
        int rb=s&1, base=(dir*2+rb)*HD;
        hs[tid]=__ldcg(&d_hbuf[base+tid]);
        __syncthreads();
        float p0=0.f,p1=0.f,p2=0.f,p3=0.f;
        const float* hb=hs+seg;
#pragma unroll
        for(int ii=0;ii<64;ii+=4){
            p0=fmaf(w[ii],  hb[ii*8],    p0);
            p1=fmaf(w[ii+1],hb[ii*8+8],  p1);
            p2=fmaf(w[ii+2],hb[ii*8+16], p2);
            p3=fmaf(w[ii+3],hb[ii*8+24], p3);
        }
        float p=(p0+p1)+(p2+p3);
        p+=__shfl_xor_sync(~0u,p,1); p+=__shfl_xor_sync(~0u,p,2); p+=__shfl_xor_sync(~0u,p,4);
        float val=p+xgs[s*64+g*16+wp];
        float gi=__shfl_sync(~0u,val,0),  gf=__shfl_sync(~0u,val,8);
        float gg2=__shfl_sync(~0u,val,16),go=__shfl_sync(~0u,val,24);
        c=fsig(gf)*c+fsig(gi)*ftanh(gg2);
        float h=fsig(go)*ftanh(c);
        if(l==0){
            __stcg(&d_hbuf[(dir*2+(rb^1))*HD+j],h);
            int tt=dir?(127-s):s;
            __stcg(&d_hcat[(size_t)tt*(2*HD)+dir*HD+j],h);
        }
        __syncthreads();
        if(tid==0) st_rel(&flags[blk], s+1);
        if(tid<32){
            while(!__all_sync(0xffffffffu, ld_acq(&flags[tid])>=s+1)){}
        }
        __syncthreads();
    }
}

__global__ void k_us(const float* __restrict__ UW,const float* __restrict__ Ub,
                     const float* __restrict__ SW,const float* __restrict__ Sb){
    int jt=blockIdx.x, m=blockIdx.y, j0=jt*8, t=threadIdx.x;
    const float* W=m?SW:UW; const float* bb=m?Sb:Ub;
    __shared__ float Wt[8][2*HD];
    const float4* Wv=(const float4*)(W+(size_t)j0*2*HD);
    float4* Ws=(float4*)Wt;
    for(int i=t;i<8*2*HD/4;i+=128) Ws[i]=Wv[i];
    __syncthreads();
    float acc[8];
#pragma unroll
    for(int cc=0;cc<8;cc++) acc[cc]=0.0f;
    const float4* h4=(const float4*)&d_hcat[(size_t)t*2*HD];
    for(int k=0;k<2*HD/4;k++){
        float4 hv=h4[k];
#pragma unroll
        for(int cc=0;cc<8;cc++){
            float4 wv=*(const float4*)&Wt[cc][k*4];
            acc[cc]=fmaf(hv.x,wv.x,fmaf(hv.y,wv.y,fmaf(hv.z,wv.z,fmaf(hv.w,wv.w,acc[cc]))));
        }
    }
#pragma unroll
    for(int cc=0;cc<8;cc++){
        float x=acc[cc]+bb[j0+cc];
        if(m) d_s[t*HD+j0+cc]=log1pf(expf(-fabsf(x)))+fmaxf(x,0.0f);
        else  d_u[t*HD+j0+cc]=x;
    }
}

__global__ void k_sample(){
    int r=blockIdx.x, j=threadIdx.x;
    int t = (r<128)? r : ((r-128)&127);
    u32 k0,k1; unsigned flat;
    if(r<128){ k0=d_keys[0]; k1=d_keys[1]; flat=(unsigned)(r*HD+j); }
    else     { k0=d_keys[2]; k1=d_keys[3]; flat=(unsigned)((r-128)*HD+j); }
    uint2 o=tf2x32(k0,k1,0u,flat);
    float n=jnormal(o.x^o.y);
    float uu=d_u[t*HD+j], ss=d_s[t*HD+j];
    d_zb[(size_t)r*HD+j]=__float2bfloat16_rn(uu+ss*n);
    if(r<128){
        float v=0.5f*(ss*ss+uu*uu-1.0f-2.0f*logf(ss));
#pragma unroll
        for(int o2=16;o2;o2>>=1) v+=__shfl_xor_sync(~0u,v,o2);
        __shared__ float sw[16];
        if((j&31)==0) sw[j>>5]=v;
        __syncthreads();
        if(j<16){ v=sw[j];
            for(int o2=8;o2;o2>>=1) v+=__shfl_xor_sync(0xffffu,v,o2);
            if(j==0) atomicAdd(&d_kl,v);
        }
    }
}

__global__ void __launch_bounds__(256) k_mma(const float* __restrict__ fb,const float* __restrict__ gb,
        const int* __restrict__ wl1,const int* __restrict__ wl2){
    __shared__ __align__(16) __nv_bfloat16 As[128*72];
    __shared__ __align__(16) __nv_bfloat16 Bs[128*72];
    __shared__ float sbias[128];
    __shared__ float red_m[128][4];
    __shared__ float red_s[128][4];
    int tid=threadIdx.x, cx=blockIdx.x, ry=blockIdx.y;
    int col0=cx*128, row0=ry*128;
    const __nv_bfloat16* Wsrc = ry? d_gWb : d_fWb;
    const float* bb = ry? gb : fb;
    if(tid<128) sbias[tid]=bb[col0+tid];
    int lane=tid&31, warp=tid>>5, rw=warp>>2, cw=warp&3;
    float acc[4][4][4];
#pragma unroll
    for(int mt=0;mt<4;mt++)
#pragma unroll
        for(int nt=0;nt<4;nt++)
#pragma unroll
            for(int q=0;q<4;q++) acc[mt][nt][q]=0.0f;
    int lr=tid>>1, half=(tid&1);
    const uint4* gA=(const uint4*)(d_zb+(size_t)(row0+lr)*HD);
    const uint4* gB=(const uint4*)(Wsrc+(size_t)(col0+lr)*HD);
    const __nv_bfloat16* Ab=As+(size_t)(rw*64+(lane>>2))*72;
    const __nv_bfloat16* Bb=Bs+(size_t)(cw*32+(lane>>2))*72;
    for(int ch=0;ch<8;ch++){
#pragma unroll
        for(int i=0;i<4;i++){
            uint4 v=gA[ch*8+half*4+i];
            *(uint4*)(As+(size_t)lr*72+half*32+i*8)=v;
            uint4 w2=gB[ch*8+half*4+i];
            *(uint4*)(Bs+(size_t)lr*72+half*32+i*8)=w2;
        }
        __syncthreads();
#pragma unroll
        for(int ks=0;ks<4;ks++){
            int kc=ks*16+(lane&3)*2;
            u32 a[4][4], b2[4][2];
#pragma unroll
            for(int mt=0;mt<4;mt++){
                a[mt][0]=*(const u32*)(Ab+mt*16*72+kc);
                a[mt][1]=*(const u32*)(Ab+(mt*16+8)*72+kc);
                a[mt][2]=*(const u32*)(Ab+mt*16*72+kc+8);
                a[mt][3]=*(const u32*)(Ab+(mt*16+8)*72+kc+8);
            }
#pragma unroll
            for(int nt=0;nt<4;nt++){
                b2[nt][0]=*(const u32*)(Bb+nt*8*72+kc);
                b2[nt][1]=*(const u32*)(Bb+nt*8*72+kc+8);
            }
#pragma unroll
            for(int mt=0;mt<4;mt++)
#pragma unroll
                for(int nt=0;nt<4;nt++)
                    asm volatile("mma.sync.aligned.m16n8k16.row.col.f32.bf16.bf16.f32 "
                        "{%0,%1,%2,%3},{%4,%5,%6,%7},{%8,%9},{%0,%1,%2,%3};"
                        :"+f"(acc[mt][nt][0]),"+f"(acc[mt][nt][1]),"+f"(acc[mt][nt][2]),"+f"(acc[mt][nt][3])
                        :"r"(a[mt][0]),"r"(a[mt][1]),"r"(a[mt][2]),"r"(a[mt][3]),
                         "r"(b2[nt][0]),"r"(b2[nt][1]));
        }
        __syncthreads();
    }
#pragma unroll
    for(int mt=0;mt<4;mt++)
#pragma unroll
        for(int nt=0;nt<4;nt++){
            float b0=sbias[cw*32+nt*8+(lane&3)*2], b1=sbias[cw*32+nt*8+(lane&3)*2+1];
            acc[mt][nt][0]+=b0; acc[mt][nt][1]+=b1;
            acc[mt][nt][2]+=b0; acc[mt][nt][3]+=b1;
        }
#pragma unroll
    for(int mt=0;mt<4;mt++)
#pragma unroll
        for(int h=0;h<2;h++){
            float m=-1e30f;
#pragma unroll
            for(int nt=0;nt<4;nt++) m=fmaxf(m,fmaxf(acc[mt][nt][h*2],acc[mt][nt][h*2+1]));
            m=fmaxf(m,__shfl_xor_sync(~0u,m,1));
            m=fmaxf(m,__shfl_xor_sync(~0u,m,2));
            if((lane&3)==0) red_m[rw*64+mt*16+(lane>>2)+h*8][cw]=m;
        }
    __syncthreads();
#pragma unroll
    for(int mt=0;mt<4;mt++)
#pragma unroll
        for(int h=0;h<2;h++){
            int rloc=rw*64+mt*16+(lane>>2)+h*8;
            int rg=row0+rloc;
            float M=fmaxf(fmaxf(red_m[rloc][0],red_m[rloc][1]),fmaxf(red_m[rloc][2],red_m[rloc][3]));
            int tw=(rg<128)?wl1[rg]:wl2[(rg-128)>>7];
            int tloc=tw-col0;
            float s=0.0f;
#pragma unroll
            for(int nt=0;nt<4;nt++){
                int c0=cw*32+nt*8+(lane&3)*2;
                float v0=acc[mt][nt][h*2], v1=acc[mt][nt][h*2+1];
                if(c0==tloc)   d_tgt[rg]=v0;
                if(c0+1==tloc) d_tgt[rg]=v1;
                s+=__expf(v0-M)+__expf(v1-M);
            }
            s+=__shfl_xor_sync(~0u,s,1);
            s+=__shfl_xor_sync(~0u,s,2);
            if((lane&3)==0) red_s[rloc][cw]=s;
        }
    __syncthreads();
    if(tid<128){
        float M=fmaxf(fmaxf(red_m[tid][0],red_m[tid][1]),fmaxf(red_m[tid][2],red_m[tid][3]));
        float S=red_s[tid][0]+red_s[tid][1]+red_s[tid][2]+red_s[tid][3];
        int rg=row0+tid;
        d_pm[(size_t)rg*NCT+cx]=M;
        d_ps[(size_t)rg*NCT+cx]=S;
    }
}

__global__ void k_final(){
    int r=blockIdx.x, tid=threadIdx.x;
    __shared__ float sw[4]; __shared__ float sM;
    float M=-1e30f;
    for(int i=tid;i<NCT;i+=128) M=fmaxf(M,d_pm[(size_t)r*NCT+i]);
    for(int o=16;o;o>>=1) M=fmaxf(M,__shfl_xor_sync(~0u,M,o));
    if((tid&31)==0) sw[tid>>5]=M;
    __syncthreads();
    if(tid==0) sM=fmaxf(fmaxf(sw[0],sw[1]),fmaxf(sw[2],sw[3]));
    __syncthreads();
    float Mf=sM, S=0.0f;
    for(int i=tid;i<NCT;i+=128) S+=d_ps[(size_t)r*NCT+i]*expf(d_pm[(size_t)r*NCT+i]-Mf);
    for(int o=16;o;o>>=1) S+=__shfl_xor_sync(~0u,S,o);
    if((tid&31)==0) sw[tid>>5]=S;
    __syncthreads();
    if(tid==0){
        S=sw[0]+sw[1]+sw[2]+sw[3];
        float lp=d_tgt[r]-(logf(S)+Mf);
        float wg=(r<128)?1.0f:(1.0f/16.0f);
        atomicAdd(&d_acc,lp*wg);
    }
}

__global__ void k_out(float* out){ out[0]=-d_kl+d_acc; }

extern "C" void kernel_launch(void* const* d_in, const int* in_sizes, int n_in,
                              void* d_out, int out_size){
    const int*   wl1=(const int*)d_in[0];
    const int*   wl2=(const int*)d_in[1];
    const float* emb=(const float*)d_in[2];
    const float* Wihf=(const float*)d_in[3];
    const float* Whhf=(const float*)d_in[4];
    const float* bihf=(const float*)d_in[5];
    const float* bhhf=(const float*)d_in[6];
    const float* Wihb=(const float*)d_in[7];
    const float* Whhb=(const float*)d_in[8];
    const float* bihb=(const float*)d_in[9];
    const float* bhhb=(const float*)d_in[10];
    const float* UW=(const float*)d_in[11];
    const float* Ub=(const float*)d_in[12];
    const float* SW=(const float*)d_in[13];
    const float* Sb=(const float*)d_in[14];
    const float* fW=(const float*)d_in[15];
    const float* fb=(const float*)d_in[16];
    const float* gW=(const float*)d_in[17];
    const float* gb=(const float*)d_in[18];
    k_init<<<256,128>>>(wl1,emb);
    k_cvt<<<16000,256>>>(fW,gW);
    k_xg<<<dim3(128,2),128>>>(Wihf,bihf,bhhf,Wihb,bihb,bhhb);
    k_lstm<<<64,512>>>(Whhf,Whhb);
    k_us<<<dim3(64,2),128>>>(UW,Ub,SW,Sb);
    k_sample<<<RTOT,512>>>();
    k_mma<<<dim3(NCT,17),256>>>(fb,gb,wl1,wl2);
    k_final<<<RTOT,128>>>();
    k_out<<<1,1>>>((float*)d_out);
}

// round 8
// speedup vs baseline: 1.7458x; 1.7458x over previous
#include <cuda_runtime.h>
#include <cuda_bf16.h>
typedef unsigned int u32; typedef unsigned long long u64;

#define NT1 128
#define ED  256
#define HD  512
#define G4  2048
#define RTOT 2176
#define NCT 250
#define VV  32000

__device__ float d_xT[ED*NT1];
__device__ float d_xg[2*NT1*G4];
__device__ u64  d_hb64[2*2*HD];      // [dir][parity][unit] = {tag:32, h_bits:32}
__device__ float d_hcat[NT1*2*HD];
__device__ float d_u[NT1*HD];
__device__ float d_s[NT1*HD];
__device__ __align__(16) __nv_bfloat16 d_zb[(size_t)RTOT*HD];
__device__ __align__(16) __nv_bfloat16 d_fWb[(size_t)VV*HD];
__device__ __align__(16) __nv_bfloat16 d_gWb[(size_t)VV*HD];
__device__ float d_pm[(size_t)RTOT*NCT];
__device__ float d_ps[(size_t)RTOT*NCT];
__device__ float d_tgt[RTOT];
__device__ u32 d_keys[4];
__device__ float d_kl, d_acc;

__device__ __forceinline__ uint2 tf2x32(u32 k0,u32 k1,u32 c0,u32 c1){
    u32 ks2=0x1BD11BDAu^k0^k1, x0=c0+k0, x1=c1+k1;
#define TFR(r) {x0+=x1; x1=__funnelshift_l(x1,x1,r); x1^=x0;}
    TFR(13)TFR(15)TFR(26)TFR(6)  x0+=k1;  x1+=ks2+1u;
    TFR(17)TFR(29)TFR(16)TFR(24) x0+=ks2; x1+=k0+2u;
    TFR(13)TFR(15)TFR(26)TFR(6)  x0+=k0;  x1+=k1+3u;
    TFR(17)TFR(29)TFR(16)TFR(24) x0+=k1;  x1+=ks2+4u;
    TFR(13)TFR(15)TFR(26)TFR(6)  x0+=ks2; x1+=k0+5u;
#undef TFR
    return make_uint2(x0,x1);
}
__device__ __forceinline__ float jnormal(u32 bits){
    float f=__uint_as_float((bits>>9)|0x3f800000u)-1.0f;
    const float lo=__int_as_float(0xBF7FFFFF);
    float u=fmaxf(lo, f*(1.0f-lo)+lo);
    float w=-log1pf(-u*u), p;
    if(w<5.0f){ w-=2.5f;
        p=2.81022636e-08f;           p=fmaf(p,w,3.43273939e-07f);
        p=fmaf(p,w,-3.5233877e-06f); p=fmaf(p,w,-4.39150654e-06f);
        p=fmaf(p,w,0.00021858087f);  p=fmaf(p,w,-0.00125372503f);
        p=fmaf(p,w,-0.00417768164f); p=fmaf(p,w,0.246640727f);
        p=fmaf(p,w,1.50140941f);
    } else { w=sqrtf(w)-3.0f;
        p=-0.000200214257f;          p=fmaf(p,w,0.000100950558f);
        p=fmaf(p,w,0.00134934322f);  p=fmaf(p,w,-0.00367342844f);
        p=fmaf(p,w,0.00573950773f);  p=fmaf(p,w,-0.0076224613f);
        p=fmaf(p,w,0.00943887047f);  p=fmaf(p,w,1.00167406f);
        p=fmaf(p,w,2.83297682f);
    }
    return 1.41421354f*(p*u);
}
__device__ __forceinline__ float sigf(float x){ return 1.0f/(1.0f+expf(-x)); }
__device__ __forceinline__ float fsig(float x){ return __fdividef(1.0f,1.0f+__expf(-x)); }
__device__ __forceinline__ float ftanh(float x){ return 1.0f-__fdividef(2.0f,__expf(2.0f*x)+1.0f); }

__global__ void k_init(const int* __restrict__ wl1, const float* __restrict__ emb){
    int tid=blockIdx.x*blockDim.x+threadIdx.x;
    int t=tid&127, k=tid>>7;
    d_xT[k*NT1+t]=emb[(size_t)wl1[t]*ED+k];
    if(tid<2048) d_hb64[tid]=0ull;   // tag 0 = h_0 valid (value 0.0f)
    if(tid==0){
        d_kl=0.0f; d_acc=0.0f;
        uint2 a=tf2x32(0u,42u,0u,0u), b=tf2x32(0u,42u,0u,1u);
        d_keys[0]=a.x; d_keys[1]=a.y; d_keys[2]=b.x; d_keys[3]=b.y;
    }
}

__global__ void k_cvt(const float* __restrict__ fW,const float* __restrict__ gW){
    size_t i=((size_t)blockIdx.x*blockDim.x+threadIdx.x)*4;
    float4 a=*(const float4*)(fW+i);
    __nv_bfloat162* o=(__nv_bfloat162*)(d_fWb+i);
    o[0]=__floats2bfloat162_rn(a.x,a.y); o[1]=__floats2bfloat162_rn(a.z,a.w);
    float4 b=*(const float4*)(gW+i);
    __nv_bfloat162* o2=(__nv_bfloat162*)(d_gWb+i);
    o2[0]=__floats2bfloat162_rn(b.x,b.y); o2[1]=__floats2bfloat162_rn(b.z,b.w);
}

__global__ void k_xg(const float* __restrict__ Wf,const float* __restrict__ bif,
                     const float* __restrict__ bhf,const float* __restrict__ Wb,
                     const float* __restrict__ bib,const float* __restrict__ bhb){
    int dir=blockIdx.y, j0=blockIdx.x*16, t=threadIdx.x;
    const float* W = dir?Wb:Wf; const float* b1=dir?bib:bif; const float* b2=dir?bhb:bhf;
    __shared__ float Ws[16][ED]; __shared__ float bs[16];
    for(int i=t;i<16*ED;i+=128) Ws[i>>8][i&255]=W[(size_t)(j0+(i>>8))*ED+(i&255)];
    if(t<16) bs[t]=b1[j0+t]+b2[j0+t];
    __syncthreads();
    int ts = dir?(127-t):t;
    float acc[16];
#pragma unroll
    for(int c=0;c<16;c++) acc[c]=0.0f;
    for(int k=0;k<ED;k++){
        float xv=d_xT[k*NT1+ts];
#pragma unroll
        for(int c=0;c<16;c++) acc[c]=fmaf(xv,Ws[c][k],acc[c]);
    }
#pragma unroll
    for(int c=0;c<16;c++) d_xg[(size_t)(dir*NT1+t)*G4+j0+c]=acc[c]+bs[c];
}

// persistent bi-LSTM: 32 blocks/dir x 512 thr, 16 units/block, Whh in regs.
// Sync = tagged-data polling: h published as {tag,value} u64, consumers poll the data word.
__global__ void __launch_bounds__(512,1) k_lstm(const float* __restrict__ Whf,
                                                const float* __restrict__ Whb){
    int bid=blockIdx.x, dir=bid>>5, blk=bid&31, j0=blk*16;
    int tid=threadIdx.x, wp=tid>>5, l=tid&31, g=l>>3, seg=l&7;
    int j=j0+wp;
    const float* Whh = dir?Whb:Whf;
    float w[64];
    {
        const float* wr=Whh+(size_t)(g*HD+j)*HD+seg;
#pragma unroll
        for(int ii=0;ii<64;ii++) w[ii]=wr[ii*8];
    }
    __shared__ float hs[HD];
    __shared__ float xgs[NT1*64];
    for(int idx=tid; idx<NT1*64; idx+=512){
        int s=idx>>6, r=idx&63, gg=r>>4, uu=r&15;
        xgs[idx]=d_xg[(size_t)(dir*NT1+s)*G4 + gg*HD + j0+uu];
    }
    float c=0.0f;
    u64* buf0=&d_hb64[dir*2*HD];
    __syncthreads();
    for(int s=0;s<NT1;s++){
        // acquire h_s: poll tagged word (single L2 hop carries data+flag)
        const u64* pw=&buf0[(s&1)*HD + tid];
        u32 got=0; float hv=0.0f;
        do{
            if(!got){
                u64 v=__ldcg(pw);
                if((u32)(v>>32)>=(u32)s){ hv=__uint_as_float((u32)v); got=1; }
            }
        }while(!__all_sync(0xffffffffu,got));
        hs[tid]=hv;
        __syncthreads();
        float p0=0.f,p1=0.f,p2=0.f,p3=0.f;
        const float* hb=hs+seg;
#pragma unroll
        for(int ii=0;ii<64;ii+=4){
            p0=fmaf(w[ii],  hb[ii*8],    p0);
            p1=fmaf(w[ii+1],hb[ii*8+8],  p1);
            p2=fmaf(w[ii+2],hb[ii*8+16], p2);
            p3=fmaf(w[ii+3],hb[ii*8+24], p3);
        }
        float p=(p0+p1)+(p2+p3);
        p+=__shfl_xor_sync(~0u,p,1); p+=__shfl_xor_sync(~0u,p,2); p+=__shfl_xor_sync(~0u,p,4);
        float val=p+xgs[s*64+g*16+wp];
        float gi=__shfl_sync(~0u,val,0),  gf=__shfl_sync(~0u,val,8);
        float gg2=__shfl_sync(~0u,val,16),go=__shfl_sync(~0u,val,24);
        c=fsig(gf)*c+fsig(gi)*ftanh(gg2);
        float h=fsig(go)*ftanh(c);
        if(l==0){
            u64 pk=(((u64)(u32)(s+1))<<32)|(u64)__float_as_uint(h);
            __stcg(&buf0[((s+1)&1)*HD + j], pk);
            int tt=dir?(127-s):s;
            __stcg(&d_hcat[(size_t)tt*(2*HD)+dir*HD+j],h);
        }
        __syncthreads();   // protect hs[] from next-step overwrite
    }
}

__global__ void k_us(const float* __restrict__ UW,const float* __restrict__ Ub,
                     const float* __restrict__ SW,const float* __restrict__ Sb){
    int jt=blockIdx.x, m=blockIdx.y, j0=jt*8, t=threadIdx.x;
    const float* W=m?SW:UW; const float* bb=m?Sb:Ub;
    __shared__ float Wt[8][2*HD];
    const float4* Wv=(const float4*)(W+(size_t)j0*2*HD);
    float4* Ws=(float4*)Wt;
    for(int i=t;i<8*2*HD/4;i+=128) Ws[i]=Wv[i];
    __syncthreads();
    float acc[8];
#pragma unroll
    for(int cc=0;cc<8;cc++) acc[cc]=0.0f;
    const float4* h4=(const float4*)&d_hcat[(size_t)t*2*HD];
    for(int k=0;k<2*HD/4;k++){
        float4 hv=h4[k];
#pragma unroll
        for(int cc=0;cc<8;cc++){
            float4 wv=*(const float4*)&Wt[cc][k*4];
            acc[cc]=fmaf(hv.x,wv.x,fmaf(hv.y,wv.y,fmaf(hv.z,wv.z,fmaf(hv.w,wv.w,acc[cc]))));
        }
    }
#pragma unroll
    for(int cc=0;cc<8;cc++){
        float x=acc[cc]+bb[j0+cc];
        if(m) d_s[t*HD+j0+cc]=log1pf(expf(-fabsf(x)))+fmaxf(x,0.0f);
        else  d_u[t*HD+j0+cc]=x;
    }
}

__global__ void k_sample(){
    int r=blockIdx.x, j=threadIdx.x;
    int t = (r<128)? r : ((r-128)&127);
    u32 k0,k1; unsigned flat;
    if(r<128){ k0=d_keys[0]; k1=d_keys[1]; flat=(unsigned)(r*HD+j); }
    else     { k0=d_keys[2]; k1=d_keys[3]; flat=(unsigned)((r-128)*HD+j); }
    uint2 o=tf2x32(k0,k1,0u,flat);
    float n=jnormal(o.x^o.y);
    float uu=d_u[t*HD+j], ss=d_s[t*HD+j];
    d_zb[(size_t)r*HD+j]=__float2bfloat16_rn(uu+ss*n);
    if(r<128){
        float v=0.5f*(ss*ss+uu*uu-1.0f-2.0f*logf(ss));
#pragma unroll
        for(int o2=16;o2;o2>>=1) v+=__shfl_xor_sync(~0u,v,o2);
        __shared__ float sw[16];
        if((j&31)==0) sw[j>>5]=v;
        __syncthreads();
        if(j<16){ v=sw[j];
            for(int o2=8;o2;o2>>=1) v+=__shfl_xor_sync(0xffffu,v,o2);
            if(j==0) atomicAdd(&d_kl,v);
        }
    }
}

__global__ void __launch_bounds__(256) k_mma(const float* __restrict__ fb,const float* __restrict__ gb,
        const int* __restrict__ wl1,const int* __restrict__ wl2){
    __shared__ __align__(16) __nv_bfloat16 As[128*72];
    __shared__ __align__(16) __nv_bfloat16 Bs[128*72];
    __shared__ float sbias[128];
    __shared__ float red_m[128][4];
    __shared__ float red_s[128][4];
    int tid=threadIdx.x, cx=blockIdx.x, ry=blockIdx.y;
    int col0=cx*128, row0=ry*128;
    const __nv_bfloat16* Wsrc = ry? d_gWb : d_fWb;
    const float* bb = ry? gb : fb;
    if(tid<128) sbias[tid]=bb[col0+tid];
    int lane=tid&31, warp=tid>>5, rw=warp>>2, cw=warp&3;
    float acc[4][4][4];
#pragma unroll
    for(int mt=0;mt<4;mt++)
#pragma unroll
        for(int nt=0;nt<4;nt++)
#pragma unroll
            for(int q=0;q<4;q++) acc[mt][nt][q]=0.0f;
    int lr=tid>>1, half=(tid&1);
    const uint4* gA=(const uint4*)(d_zb+(size_t)(row0+lr)*HD);
    const uint4* gB=(const uint4*)(Wsrc+(size_t)(col0+lr)*HD);
    const __nv_bfloat16* Ab=As+(size_t)(rw*64+(lane>>2))*72;
    const __nv_bfloat16* Bb=Bs+(size_t)(cw*32+(lane>>2))*72;
    for(int ch=0;ch<8;ch++){
#pragma unroll
        for(int i=0;i<4;i++){
            uint4 v=gA[ch*8+half*4+i];
            *(uint4*)(As+(size_t)lr*72+half*32+i*8)=v;
            uint4 w2=gB[ch*8+half*4+i];
            *(uint4*)(Bs+(size_t)lr*72+half*32+i*8)=w2;
        }
        __syncthreads();
#pragma unroll
        for(int ks=0;ks<4;ks++){
            int kc=ks*16+(lane&3)*2;
            u32 a[4][4], b2[4][2];
#pragma unroll
            for(int mt=0;mt<4;mt++){
                a[mt][0]=*(const u32*)(Ab+mt*16*72+kc);
                a[mt][1]=*(const u32*)(Ab+(mt*16+8)*72+kc);
                a[mt][2]=*(const u32*)(Ab+mt*16*72+kc+8);
                a[mt][3]=*(const u32*)(Ab+(mt*16+8)*72+kc+8);
            }
#pragma unroll
            for(int nt=0;nt<4;nt++){
                b2[nt][0]=*(const u32*)(Bb+nt*8*72+kc);
                b2[nt][1]=*(const u32*)(Bb+nt*8*72+kc+8);
            }
#pragma unroll
            for(int mt=0;mt<4;mt++)
#pragma unroll
                for(int nt=0;nt<4;nt++)
                    asm volatile("mma.sync.aligned.m16n8k16.row.col.f32.bf16.bf16.f32 "
                        "{%0,%1,%2,%3},{%4,%5,%6,%7},{%8,%9},{%0,%1,%2,%3};"
                        :"+f"(acc[mt][nt][0]),"+f"(acc[mt][nt][1]),"+f"(acc[mt][nt][2]),"+f"(acc[mt][nt][3])
                        :"r"(a[mt][0]),"r"(a[mt][1]),"r"(a[mt][2]),"r"(a[mt][3]),
                         "r"(b2[nt][0]),"r"(b2[nt][1]));
        }
        __syncthreads();
    }
#pragma unroll
    for(int mt=0;mt<4;mt++)
#pragma unroll
        for(int nt=0;nt<4;nt++){
            float b0=sbias[cw*32+nt*8+(lane&3)*2], b1=sbias[cw*32+nt*8+(lane&3)*2+1];
            acc[mt][nt][0]+=b0; acc[mt][nt][1]+=b1;
            acc[mt][nt][2]+=b0; acc[mt][nt][3]+=b1;
        }
#pragma unroll
    for(int mt=0;mt<4;mt++)
#pragma unroll
        for(int h=0;h<2;h++){
            float m=-1e30f;
#pragma unroll
            for(int nt=0;nt<4;nt++) m=fmaxf(m,fmaxf(acc[mt][nt][h*2],acc[mt][nt][h*2+1]));
            m=fmaxf(m,__shfl_xor_sync(~0u,m,1));
            m=fmaxf(m,__shfl_xor_sync(~0u,m,2));
            if((lane&3)==0) red_m[rw*64+mt*16+(lane>>2)+h*8][cw]=m;
        }
    __syncthreads();
#pragma unroll
    for(int mt=0;mt<4;mt++)
#pragma unroll
        for(int h=0;h<2;h++){
            int rloc=rw*64+mt*16+(lane>>2)+h*8;
            int rg=row0+rloc;
            float M=fmaxf(fmaxf(red_m[rloc][0],red_m[rloc][1]),fmaxf(red_m[rloc][2],red_m[rloc][3]));
            int tw=(rg<128)?wl1[rg]:wl2[(rg-128)>>7];
            int tloc=tw-col0;
            float s=0.0f;
#pragma unroll
            for(int nt=0;nt<4;nt++){
                int c0=cw*32+nt*8+(lane&3)*2;
                float v0=acc[mt][nt][h*2], v1=acc[mt][nt][h*2+1];
                if(c0==tloc)   d_tgt[rg]=v0;
                if(c0+1==tloc) d_tgt[rg]=v1;
                s+=__expf(v0-M)+__expf(v1-M);
            }
            s+=__shfl_xor_sync(~0u,s,1);
            s+=__shfl_xor_sync(~0u,s,2);
            if((lane&3)==0) red_s[rloc][cw]=s;
        }
    __syncthreads();
    if(tid<128){
        float M=fmaxf(fmaxf(red_m[tid][0],red_m[tid][1]),fmaxf(red_m[tid][2],red_m[tid][3]));
        float S=red_s[tid][0]+red_s[tid][1]+red_s[tid][2]+red_s[tid][3];
        int rg=row0+tid;
        d_pm[(size_t)rg*NCT+cx]=M;
        d_ps[(size_t)rg*NCT+cx]=S;
    }
}

__global__ void k_final(){
    int r=blockIdx.x, tid=threadIdx.x;
    __shared__ float sw[4]; __shared__ float sM;
    float M=-1e30f;
    for(int i=tid;i<NCT;i+=128) M=fmaxf(M,d_pm[(size_t)r*NCT+i]);
    for(int o=16;o;o>>=1) M=fmaxf(M,__shfl_xor_sync(~0u,M,o));
    if((tid&31)==0) sw[tid>>5]=M;
    __syncthreads();
    if(tid==0) sM=fmaxf(fmaxf(sw[0],sw[1]),fmaxf(sw[2],sw[3]));
    __syncthreads();
    float Mf=sM, S=0.0f;
    for(int i=tid;i<NCT;i+=128) S+=d_ps[(size_t)r*NCT+i]*expf(d_pm[(size_t)r*NCT+i]-Mf);
    for(int o=16;o;o>>=1) S+=__shfl_xor_sync(~0u,S,o);
    if((tid&31)==0) sw[tid>>5]=S;
    __syncthreads();
    if(tid==0){
        S=sw[0]+sw[1]+sw[2]+sw[3];
        float lp=d_tgt[r]-(logf(S)+Mf);
        float wg=(r<128)?1.0f:(1.0f/16.0f);
        atomicAdd(&d_acc,lp*wg);
    }
}

__global__ void k_out(float* out){ out[0]=-d_kl+d_acc; }

extern "C" void kernel_launch(void* const* d_in, const int* in_sizes, int n_in,
                              void* d_out, int out_size){
    const int*   wl1=(const int*)d_in[0];
    const int*   wl2=(const int*)d_in[1];
    const float* emb=(const float*)d_in[2];
    const float* Wihf=(const float*)d_in[3];
    const float* Whhf=(const float*)d_in[4];
    const float* bihf=(const float*)d_in[5];
    const float* bhhf=(const float*)d_in[6];
    const float* Wihb=(const float*)d_in[7];
    const float* Whhb=(const float*)d_in[8];
    const float* bihb=(const float*)d_in[9];
    const float* bhhb=(const float*)d_in[10];
    const float* UW=(const float*)d_in[11];
    const float* Ub=(const float*)d_in[12];
    const float* SW=(const float*)d_in[13];
    const float* Sb=(const float*)d_in[14];
    const float* fW=(const float*)d_in[15];
    const float* fb=(const float*)d_in[16];
    const float* gW=(const float*)d_in[17];
    const float* gb=(const float*)d_in[18];
    k_init<<<256,128>>>(wl1,emb);
    k_cvt<<<16000,256>>>(fW,gW);
    k_xg<<<dim3(128,2),128>>>(Wihf,bihf,bhhf,Wihb,bihb,bhhb);
    k_lstm<<<64,512>>>(Whhf,Whhb);
    k_us<<<dim3(64,2),128>>>(UW,Ub,SW,Sb);
    k_sample<<<RTOT,512>>>();
    k_mma<<<dim3(NCT,17),256>>>(fb,gb,wl1,wl2);
    k_final<<<RTOT,128>>>();
    k_out<<<1,1>>>((float*)d_out);
}

// round 10
// speedup vs baseline: 1.7529x; 1.0041x over previous
#include <cuda_runtime.h>
#include <cuda_bf16.h>
typedef unsigned int u32; typedef unsigned long long u64;

#define NT1 128
#define ED  256
#define HD  512
#define G4  2048
#define RTOT 2176
#define NCT 250
#define VV  32000
#define SM_A 0
#define SM_B 36864
#define SM_BIAS 73728
#define SM_RM 74240
#define SM_RS 76288
#define SM_TOT 78336
#define STAGE_B 18432

__device__ float d_xT[ED*NT1];
__device__ float d_xg[2*NT1*G4];
__device__ u64  d_hb64[2*2*HD];
__device__ float d_hcat[NT1*2*HD];
__device__ float d_u[NT1*HD];
__device__ float d_s[NT1*HD];
__device__ __align__(16) __nv_bfloat16 d_zb[(size_t)RTOT*HD];
__device__ __align__(16) __nv_bfloat16 d_fWb[(size_t)VV*HD];
__device__ __align__(16) __nv_bfloat16 d_gWb[(size_t)VV*HD];
__device__ float d_pm[(size_t)RTOT*NCT];
__device__ float d_ps[(size_t)RTOT*NCT];
__device__ float d_tgt[RTOT];
__device__ u32 d_keys[4];
__device__ float d_kl, d_acc;

__device__ __forceinline__ uint2 tf2x32(u32 k0,u32 k1,u32 c0,u32 c1){
    u32 ks2=0x1BD11BDAu^k0^k1, x0=c0+k0, x1=c1+k1;
#define TFR(r) {x0+=x1; x1=__funnelshift_l(x1,x1,r); x1^=x0;}
    TFR(13)TFR(15)TFR(26)TFR(6)  x0+=k1;  x1+=ks2+1u;
    TFR(17)TFR(29)TFR(16)TFR(24) x0+=ks2; x1+=k0+2u;
    TFR(13)TFR(15)TFR(26)TFR(6)  x0+=k0;  x1+=k1+3u;
    TFR(17)TFR(29)TFR(16)TFR(24) x0+=k1;  x1+=ks2+4u;
    TFR(13)TFR(15)TFR(26)TFR(6)  x0+=ks2; x1+=k0+5u;
#undef TFR
    return make_uint2(x0,x1);
}
__device__ __forceinline__ float jnormal(u32 bits){
    float f=__uint_as_float((bits>>9)|0x3f800000u)-1.0f;
    const float lo=__int_as_float(0xBF7FFFFF);
    float u=fmaxf(lo, f*(1.0f-lo)+lo);
    float w=-log1pf(-u*u), p;
    if(w<5.0f){ w-=2.5f;
        p=2.81022636e-08f;           p=fmaf(p,w,3.43273939e-07f);
        p=fmaf(p,w,-3.5233877e-06f); p=fmaf(p,w,-4.39150654e-06f);
        p=fmaf(p,w,0.00021858087f);  p=fmaf(p,w,-0.00125372503f);
        p=fmaf(p,w,-0.00417768164f); p=fmaf(p,w,0.246640727f);
        p=fmaf(p,w,1.50140941f);
    } else { w=sqrtf(w)-3.0f;
        p=-0.000200214257f;          p=fmaf(p,w,0.000100950558f);
        p=fmaf(p,w,0.00134934322f);  p=fmaf(p,w,-0.00367342844f);
        p=fmaf(p,w,0.00573950773f);  p=fmaf(p,w,-0.0076224613f);
        p=fmaf(p,w,0.00943887047f);  p=fmaf(p,w,1.00167406f);
        p=fmaf(p,w,2.83297682f);
    }
    return 1.41421354f*(p*u);
}
__device__ __forceinline__ float sigf(float x){ return 1.0f/(1.0f+expf(-x)); }
__device__ __forceinline__ float fsig(float x){ return __fdividef(1.0f,1.0f+__expf(-x)); }
__device__ __forceinline__ float ftanh(float x){ return 1.0f-__fdividef(2.0f,__expf(2.0f*x)+1.0f); }
__device__ __forceinline__ u32 s2u(const void* p){
    u32 a; asm("{ .reg .u64 t; cvta.to.shared.u64 t, %1; cvt.u32.u64 %0, t; }":"=r"(a):"l"(p)); return a;
}
__device__ __forceinline__ void cpa16(u32 d,const void* s){
    asm volatile("cp.async.cg.shared.global [%0],[%1],16;"::"r"(d),"l"(s):"memory");
}

__global__ void k_init(const int* __restrict__ wl1, const float* __restrict__ emb){
    int tid=blockIdx.x*blockDim.x+threadIdx.x;
    int t=tid&127, k=tid>>7;
    d_xT[k*NT1+t]=emb[(size_t)wl1[t]*ED+k];
    if(tid<2048) d_hb64[tid]=0ull;
    if(tid==0){
        d_kl=0.0f; d_acc=0.0f;
        uint2 a=tf2x32(0u,42u,0u,0u), b=tf2x32(0u,42u,0u,1u);
        d_keys[0]=a.x; d_keys[1]=a.y; d_keys[2]=b.x; d_keys[3]=b.y;
    }
}

__global__ void k_cvt(const float* __restrict__ fW,const float* __restrict__ gW){
    size_t i=((size_t)blockIdx.x*blockDim.x+threadIdx.x)*4;
    float4 a=*(const float4*)(fW+i);
    __nv_bfloat162* o=(__nv_bfloat162*)(d_fWb+i);
    o[0]=__floats2bfloat162_rn(a.x,a.y); o[1]=__floats2bfloat162_rn(a.z,a.w);
    float4 b=*(const float4*)(gW+i);
    __nv_bfloat162* o2=(__nv_bfloat162*)(d_gWb+i);
    o2[0]=__floats2bfloat162_rn(b.x,b.y); o2[1]=__floats2bfloat162_rn(b.z,b.w);
}

__global__ void k_xg(const float* __restrict__ Wf,const float* __restrict__ bif,
                     const float* __restrict__ bhf,const float* __restrict__ Wb,
                     const float* __restrict__ bib,const float* __restrict__ bhb){
    int dir=blockIdx.y, j0=blockIdx.x*16, t=threadIdx.x;
    const float* W = dir?Wb:Wf; const float* b1=dir?bib:bif; const float* b2=dir?bhb:bhf;
    __shared__ float Ws[16][ED]; __shared__ float bs[16];
    for(int i=t;i<16*ED;i+=128) Ws[i>>8][i&255]=W[(size_t)(j0+(i>>8))*ED+(i&255)];
    if(t<16) bs[t]=b1[j0+t]+b2[j0+t];
    __syncthreads();
    int ts = dir?(127-t):t;
    float acc[16];
#pragma unroll
    for(int c=0;c<16;c++) acc[c]=0.0f;
    for(int k=0;k<ED;k++){
        float xv=d_xT[k*NT1+ts];
#pragma unroll
        for(int c=0;c<16;c++) acc[c]=fmaf(xv,Ws[c][k],acc[c]);
    }
#pragma unroll
    for(int c=0;c<16;c++) d_xg[(size_t)(dir*NT1+t)*G4+j0+c]=acc[c]+bs[c];
}

__global__ void __launch_bounds__(512,1) k_lstm(const float* __restrict__ Whf,
                                                const float* __restrict__ Whb){
    int bid=blockIdx.x, dir=bid>>5, blk=bid&31, j0=blk*16;
    int tid=threadIdx.x, wp=tid>>5, l=tid&31, g=l>>3, seg=l&7;
    int j=j0+wp;
    const float* Whh = dir?Whb:Whf;
    float w[64];
    {
        const float* wr=Whh+(size_t)(g*HD+j)*HD+seg;
#pragma unroll
        for(int ii=0;ii<64;ii++) w[ii]=wr[ii*8];
    }
    __shared__ float hs[HD];
    __shared__ float xgs[NT1*64];
    for(int idx=tid; idx<NT1*64; idx+=512){
        int s=idx>>6, r=idx&63, gg=r>>4, uu=r&15;
        xgs[idx]=d_xg[(size_t)(dir*NT1+s)*G4 + gg*HD + j0+uu];
    }
    float c=0.0f;
    u64* buf0=&d_hb64[dir*2*HD];
    __syncthreads();
    for(int s=0;s<NT1;s++){
        const u64* pw=&buf0[(s&1)*HD + tid];
        u32 got=0; float hv=0.0f;
        do{
            if(!got){
                u64 v=__ldcg(pw);
                if((u32)(v>>32)>=(u32)s){ hv=__uint_as_float((u32)v); got=1; }
            }
        }while(!__all_sync(0xffffffffu,got));
        hs[tid]=hv;
        __syncthreads();
        float p0=0.f,p1=0.f,p2=0.f,p3=0.f;
        const float* hb=hs+seg;
#pragma unroll
        for(int ii=0;ii<64;ii+=4){
            p0=fmaf(w[ii],  hb[ii*8],    p0);
            p1=fmaf(w[ii+1],hb[ii*8+8],  p1);
            p2=fmaf(w[ii+2],hb[ii*8+16], p2);
            p3=fmaf(w[ii+3],hb[ii*8+24], p3);
        }
        float p=(p0+p1)+(p2+p3);
        p+=__shfl_xor_sync(~0u,p,1); p+=__shfl_xor_sync(~0u,p,2); p+=__shfl_xor_sync(~0u,p,4);
        float val=p+xgs[s*64+g*16+wp];
        float gi=__shfl_sync(~0u,val,0),  gf=__shfl_sync(~0u,val,8);
        float gg2=__shfl_sync(~0u,val,16),go=__shfl_sync(~0u,val,24);
        c=fsig(gf)*c+fsig(gi)*ftanh(gg2);
        float h=fsig(go)*ftanh(c);
        if(l==0){
            u64 pk=(((u64)(u32)(s+1))<<32)|(u64)__float_as_uint(h);
            __stcg(&buf0[((s+1)&1)*HD + j], pk);
            int tt=dir?(127-s):s;
            __stcg(&d_hcat[(size_t)tt*(2*HD)+dir*HD+j],h);
        }
        __syncthreads();
    }
}

__global__ void k_us(const float* __restrict__ UW,const float* __restrict__ Ub,
                     const float* __restrict__ SW,const float* __restrict__ Sb){
    int jt=blockIdx.x, m=blockIdx.y, j0=jt*8, t=threadIdx.x;
    const float* W=m?SW:UW; const float* bb=m?Sb:Ub;
    __shared__ float Wt[8][2*HD];
    const float4* Wv=(const float4*)(W+(size_t)j0*2*HD);
    float4* Ws=(float4*)Wt;
    for(int i=t;i<8*2*HD/4;i+=128) Ws[i]=Wv[i];
    __syncthreads();
    float acc[8];
#pragma unroll
    for(int cc=0;cc<8;cc++) acc[cc]=0.0f;
    const float4* h4=(const float4*)&d_hcat[(size_t)t*2*HD];
    for(int k=0;k<2*HD/4;k++){
        float4 hv=h4[k];
#pragma unroll
        for(int cc=0;cc<8;cc++){
            float4 wv=*(const float4*)&Wt[cc][k*4];
            acc[cc]=fmaf(hv.x,wv.x,fmaf(hv.y,wv.y,fmaf(hv.z,wv.z,fmaf(hv.w,wv.w,acc[cc]))));
        }
    }
#pragma unroll
    for(int cc=0;cc<8;cc++){
        float x=acc[cc]+bb[j0+cc];
        if(m) d_s[t*HD+j0+cc]=log1pf(expf(-fabsf(x)))+fmaxf(x,0.0f);
        else  d_u[t*HD+j0+cc]=x;
    }
}

__global__ void k_sample(){
    int r=blockIdx.x, j=threadIdx.x;
    int t = (r<128)? r : ((r-128)&127);
    u32 k0,k1; unsigned flat;
    if(r<128){ k0=d_keys[0]; k1=d_keys[1]; flat=(unsigned)(r*HD+j); }
    else     { k0=d_keys[2]; k1=d_keys[3]; flat=(unsigned)((r-128)*HD+j); }
    uint2 o=tf2x32(k0,k1,0u,flat);
    float n=jnormal(o.x^o.y);
    float uu=d_u[t*HD+j], ss=d_s[t*HD+j];
    d_zb[(size_t)r*HD+j]=__float2bfloat16_rn(uu+ss*n);
    if(r<128){
        float v=0.5f*(ss*ss+uu*uu-1.0f-2.0f*logf(ss));
#pragma unroll
        for(int o2=16;o2;o2>>=1) v+=__shfl_xor_sync(~0u,v,o2);
        __shared__ float sw[16];
        if((j&31)==0) sw[j>>5]=v;
        __syncthreads();
        if(j<16){ v=sw[j];
            for(int o2=8;o2;o2>>=1) v+=__shfl_xor_sync(0xffffu,v,o2);
            if(j==0) atomicAdd(&d_kl,v);
        }
    }
}

// bf16 mma.sync GEMM, cp.async double-buffered, fused bias + online log-softmax partials.
__global__ void __launch_bounds__(256) k_mma(const float* __restrict__ fb,const float* __restrict__ gb,
        const int* __restrict__ wl1,const int* __restrict__ wl2){
    extern __shared__ char dyn[];
    __nv_bfloat16* As=(__nv_bfloat16*)(dyn+SM_A);
    __nv_bfloat16* Bs=(__nv_bfloat16*)(dyn+SM_B);
    float* sbias=(float*)(dyn+SM_BIAS);
    float (*red_m)[4]=(float(*)[4])(dyn+SM_RM);
    float (*red_s)[4]=(float(*)[4])(dyn+SM_RS);
    int tid=threadIdx.x, cx=blockIdx.x, ry=blockIdx.y;
    int col0=cx*128, row0=ry*128;
    const __nv_bfloat16* Wsrc = ry? d_gWb : d_fWb;
    const float* bb = ry? gb : fb;
    if(tid<128) sbias[tid]=bb[col0+tid];
    int lane=tid&31, warp=tid>>5, rw=warp>>2, cw=warp&3;
    float acc[4][4][4];
#pragma unroll
    for(int mt=0;mt<4;mt++)
#pragma unroll
        for(int nt=0;nt<4;nt++)
#pragma unroll
            for(int q=0;q<4;q++) acc[mt][nt][q]=0.0f;
    int lr=tid>>1, half=(tid&1);
    u32 asb=s2u(As), bsb=s2u(Bs);
    const __nv_bfloat16* gA=d_zb+(size_t)(row0+lr)*HD;
    const __nv_bfloat16* gB=Wsrc+(size_t)(col0+lr)*HD;
    u32 soff=(u32)(lr*144+half*64);
#define PREFETCH(ch) { u32 bsel=(u32)(((ch)&1)*STAGE_B); \
    const __nv_bfloat16* ga=gA+(ch)*64+half*32; \
    const __nv_bfloat16* gbp=gB+(ch)*64+half*32; \
    _Pragma("unroll") for(int i=0;i<4;i++){ \
        cpa16(asb+bsel+soff+i*16, ga+i*8); \
        cpa16(bsb+bsel+soff+i*16, gbp+i*8); } \
    asm volatile("cp.async.commit_group;":::"memory"); }
    PREFETCH(0)
    for(int ch=0;ch<8;ch++){
        if(ch<7){ PREFETCH(ch+1) asm volatile("cp.async.wait_group 1;":::"memory"); }
        else    { asm volatile("cp.async.wait_group 0;":::"memory"); }
        __syncthreads();
        const __nv_bfloat16* Ab=As+(size_t)((ch&1)*128*72+(rw*64+(lane>>2))*72);
        const __nv_bfloat16* Bb=Bs+(size_t)((ch&1)*128*72+(cw*32+(lane>>2))*72);
#pragma unroll
        for(int ks=0;ks<4;ks++){
            int kc=ks*16+(lane&3)*2;
            u32 a[4][4], b2[4][2];
#pragma unroll
            for(int mt=0;mt<4;mt++){
                a[mt][0]=*(const u32*)(Ab+mt*16*72+kc);
                a[mt][1]=*(const u32*)(Ab+(mt*16+8)*72+kc);
                a[mt][2]=*(const u32*)(Ab+mt*16*72+kc+8);
                a[mt][3]=*(const u32*)(Ab+(mt*16+8)*72+kc+8);
            }
#pragma unroll
            for(int nt=0;nt<4;nt++){
                b2[nt][0]=*(const u32*)(Bb+nt*8*72+kc);
                b2[nt][1]=*(const u32*)(Bb+nt*8*72+kc+8);
            }
#pragma unroll
            for(int mt=0;mt<4;mt++)
#pragma unroll
                for(int nt=0;nt<4;nt++)
                    asm volatile("mma.sync.aligned.m16n8k16.row.col.f32.bf16.bf16.f32 "
                        "{%0,%1,%2,%3},{%4,%5,%6,%7},{%8,%9},{%0,%1,%2,%3};"
                        :"+f"(acc[mt][nt][0]),"+f"(acc[mt][nt][1]),"+f"(acc[mt][nt][2]),"+f"(acc[mt][nt][3])
                        :"r"(a[mt][0]),"r"(a[mt][1]),"r"(a[mt][2]),"r"(a[mt][3]),
                         "r"(b2[nt][0]),"r"(b2[nt][1]));
        }
        __syncthreads();
    }
#pragma unroll
    for(int mt=0;mt<4;mt++)
#pragma unroll
        for(int nt=0;nt<4;nt++){
            float b0=sbias[cw*32+nt*8+(lane&3)*2], b1=sbias[cw*32+nt*8+(lane&3)*2+1];
            acc[mt][nt][0]+=b0; acc[mt][nt][1]+=b1;
            acc[mt][nt][2]+=b0; acc[mt][nt][3]+=b1;
        }
#pragma unroll
    for(int mt=0;mt<4;mt++)
#pragma unroll
        for(int h=0;h<2;h++){
            float m=-1e30f;
#pragma unroll
            for(int nt=0;nt<4;nt++) m=fmaxf(m,fmaxf(acc[mt][nt][h*2],acc[mt][nt][h*2+1]));
            m=fmaxf(m,__shfl_xor_sync(~0u,m,1));
            m=fmaxf(m,__shfl_xor_sync(~0u,m,2));
            if((lane&3)==0) red_m[rw*64+mt*16+(lane>>2)+h*8][cw]=m;
        }
    __syncthreads();
#pragma unroll
    for(int mt=0;mt<4;mt++)
#pragma unroll
        for(int h=0;h<2;h++){
            int rloc=rw*64+mt*16+(lane>>2)+h*8;
            int rg=row0+rloc;
            float M=fmaxf(fmaxf(red_m[rloc][0],red_m[rloc][1]),fmaxf(red_m[rloc][2],red_m[rloc][3]));
            int tw=(rg<128)?wl1[rg]:wl2[(rg-128)>>7];
            int tloc=tw-col0;
            float s=0.0f;
#pragma unroll
            for(int nt=0;nt<4;nt++){
                int c0=cw*32+nt*8+(lane&3)*2;
                float v0=acc[mt][nt][h*2], v1=acc[mt][nt][h*2+1];
                if(c0==tloc)   d_tgt[rg]=v0;
                if(c0+1==tloc) d_tgt[rg]=v1;
                s+=__expf(v0-M)+__expf(v1-M);
            }
            s+=__shfl_xor_sync(~0u,s,1);
            s+=__shfl_xor_sync(~0u,s,2);
            if((lane&3)==0) red_s[rloc][cw]=s;
        }
    __syncthreads();
    if(tid<128){
        float M=fmaxf(fmaxf(red_m[tid][0],red_m[tid][1]),fmaxf(red_m[tid][2],red_m[tid][3]));
        float S=red_s[tid][0]+red_s[tid][1]+red_s[tid][2]+red_s[tid][3];
        int rg=row0+tid;
        d_pm[(size_t)rg*NCT+cx]=M;
        d_ps[(size_t)rg*NCT+cx]=S;
    }
}

__global__ void k_final(){
    int r=blockIdx.x, tid=threadIdx.x;
    __shared__ float sw[4]; __shared__ float sM;
    float M=-1e30f;
    for(int i=tid;i<NCT;i+=128) M=fmaxf(M,d_pm[(size_t)r*NCT+i]);
    for(int o=16;o;o>>=1) M=fmaxf(M,__shfl_xor_sync(~0u,M,o));
    if((tid&31)==0) sw[tid>>5]=M;
    __syncthreads();
    if(tid==0) sM=fmaxf(fmaxf(sw[0],sw[1]),fmaxf(sw[2],sw[3]));
    __syncthreads();
    float Mf=sM, S=0.0f;
    for(int i=tid;i<NCT;i+=128) S+=d_ps[(size_t)r*NCT+i]*expf(d_pm[(size_t)r*NCT+i]-Mf);
    for(int o=16;o;o>>=1) S+=__shfl_xor_sync(~0u,S,o);
    if((tid&31)==0) sw[tid>>5]=S;
    __syncthreads();
    if(tid==0){
        S=sw[0]+sw[1]+sw[2]+sw[3];
        float lp=d_tgt[r]-(logf(S)+Mf);
        float wg=(r<128)?1.0f:(1.0f/16.0f);
        atomicAdd(&d_acc,lp*wg);
    }
}

__global__ void k_out(float* out){ out[0]=-d_kl+d_acc; }

extern "C" void kernel_launch(void* const* d_in, const int* in_sizes, int n_in,
                              void* d_out, int out_size){
    const int*   wl1=(const int*)d_in[0];
    const int*   wl2=(const int*)d_in[1];
    const float* emb=(const float*)d_in[2];
    const float* Wihf=(const float*)d_in[3];
    const float* Whhf=(const float*)d_in[4];
    const float* bihf=(const float*)d_in[5];
    const float* bhhf=(const float*)d_in[6];
    const float* Wihb=(const float*)d_in[7];
    const float* Whhb=(const float*)d_in[8];
    const float* bihb=(const float*)d_in[9];
    const float* bhhb=(const float*)d_in[10];
    const float* UW=(const float*)d_in[11];
    const float* Ub=(const float*)d_in[12];
    const float* SW=(const float*)d_in[13];
    const float* Sb=(const float*)d_in[14];
    const float* fW=(const float*)d_in[15];
    const float* fb=(const float*)d_in[16];
    const float* gW=(const float*)d_in[17];
    const float* gb=(const float*)d_in[18];
    cudaFuncSetAttribute(k_mma, cudaFuncAttributeMaxDynamicSharedMemorySize, SM_TOT);
    k_init<<<256,128>>>(wl1,emb);
    k_cvt<<<16000,256>>>(fW,gW);
    k_xg<<<dim3(128,2),128>>>(Wihf,bihf,bhhf,Wihb,bihb,bhhb);
    k_lstm<<<64,512>>>(Whhf,Whhb);
    k_us<<<dim3(64,2),128>>>(UW,Ub,SW,Sb);
    k_sample<<<RTOT,512>>>();
    k_mma<<<dim3(NCT,17),256,SM_TOT>>>(fb,gb,wl1,wl2);
    k_final<<<RTOT,128>>>();
    k_out<<<1,1>>>((float*)d_out);
}

// round 11
// speedup vs baseline: 1.8944x; 1.0807x over previous
#include <cuda_runtime.h>
#include <cuda_bf16.h>
typedef unsigned int u32; typedef unsigned long long u64;

#define NT1 128
#define ED  256
#define HD  512
#define G4  2048
#define RTOT 2176
#define NCT 250
#define VV  32000
#define SM_A 0
#define SM_B 36864
#define SM_BIAS 73728
#define SM_RM 74240
#define SM_RS 76288
#define SM_TOT 78336
#define STAGE_B 18432
#define CVB 1024

__device__ float d_xT[ED*NT1];
__device__ float d_xg[2*NT1*G4];
__device__ u64  d_hb64[2*2*HD];
__device__ float d_hcat[NT1*2*HD];
__device__ float d_u[NT1*HD];
__device__ float d_s[NT1*HD];
__device__ __align__(16) __nv_bfloat16 d_zb[(size_t)RTOT*HD];
__device__ __align__(16) __nv_bfloat16 d_fWb[(size_t)VV*HD];
__device__ __align__(16) __nv_bfloat16 d_gWb[(size_t)VV*HD];
__device__ float d_pm[(size_t)RTOT*NCT];
__device__ float d_ps[(size_t)RTOT*NCT];
__device__ float d_tgt[RTOT];
__device__ u32 d_keys[4];
__device__ float d_kl, d_acc;

__device__ __forceinline__ uint2 tf2x32(u32 k0,u32 k1,u32 c0,u32 c1){
    u32 ks2=0x1BD11BDAu^k0^k1, x0=c0+k0, x1=c1+k1;
#define TFR(r) {x0+=x1; x1=__funnelshift_l(x1,x1,r); x1^=x0;}
    TFR(13)TFR(15)TFR(26)TFR(6)  x0+=k1;  x1+=ks2+1u;
    TFR(17)TFR(29)TFR(16)TFR(24) x0+=ks2; x1+=k0+2u;
    TFR(13)TFR(15)TFR(26)TFR(6)  x0+=k0;  x1+=k1+3u;
    TFR(17)TFR(29)TFR(16)TFR(24) x0+=k1;  x1+=ks2+4u;
    TFR(13)TFR(15)TFR(26)TFR(6)  x0+=ks2; x1+=k0+5u;
#undef TFR
    return make_uint2(x0,x1);
}
__device__ __forceinline__ float jnormal(u32 bits){
    float f=__uint_as_float((bits>>9)|0x3f800000u)-1.0f;
    const float lo=__int_as_float(0xBF7FFFFF);
    float u=fmaxf(lo, f*(1.0f-lo)+lo);
    float w=-log1pf(-u*u), p;
    if(w<5.0f){ w-=2.5f;
        p=2.81022636e-08f;           p=fmaf(p,w,3.43273939e-07f);
        p=fmaf(p,w,-3.5233877e-06f); p=fmaf(p,w,-4.39150654e-06f);
        p=fmaf(p,w,0.00021858087f);  p=fmaf(p,w,-0.00125372503f);
        p=fmaf(p,w,-0.00417768164f); p=fmaf(p,w,0.246640727f);
        p=fmaf(p,w,1.50140941f);
    } else { w=sqrtf(w)-3.0f;
        p=-0.000200214257f;          p=fmaf(p,w,0.000100950558f);
        p=fmaf(p,w,0.00134934322f);  p=fmaf(p,w,-0.00367342844f);
        p=fmaf(p,w,0.00573950773f);  p=fmaf(p,w,-0.0076224613f);
        p=fmaf(p,w,0.00943887047f);  p=fmaf(p,w,1.00167406f);
        p=fmaf(p,w,2.83297682f);
    }
    return 1.41421354f*(p*u);
}
__device__ __forceinline__ float sigf(float x){ return 1.0f/(1.0f+expf(-x)); }
__device__ __forceinline__ float fsig(float x){ return __fdividef(1.0f,1.0f+__expf(-x)); }
__device__ __forceinline__ float ftanh(float x){ return 1.0f-__fdividef(2.0f,__expf(2.0f*x)+1.0f); }
__device__ __forceinline__ u32 s2u(const void* p){
    u32 a; asm("{ .reg .u64 t; cvta.to.shared.u64 t, %1; cvt.u32.u64 %0, t; }":"=r"(a):"l"(p)); return a;
}
__device__ __forceinline__ void cpa16(u32 d,const void* s){
    asm volatile("cp.async.cg.shared.global [%0],[%1],16;"::"r"(d),"l"(s):"memory");
}
__device__ __forceinline__ void ldsm4(u32& r0,u32& r1,u32& r2,u32& r3,u32 a){
    asm volatile("ldmatrix.sync.aligned.m8n8.x4.shared.b16 {%0,%1,%2,%3},[%4];"
        :"=r"(r0),"=r"(r1),"=r"(r2),"=r"(r3):"r"(a));
}

__global__ void k_init(const int* __restrict__ wl1, const float* __restrict__ emb){
    int tid=blockIdx.x*blockDim.x+threadIdx.x;
    int t=tid&127, k=tid>>7;
    d_xT[k*NT1+t]=emb[(size_t)wl1[t]*ED+k];
    if(tid<2048) d_hb64[tid]=0ull;
    if(tid==0){
        d_kl=0.0f; d_acc=0.0f;
        uint2 a=tf2x32(0u,42u,0u,0u), b=tf2x32(0u,42u,0u,1u);
        d_keys[0]=a.x; d_keys[1]=a.y; d_keys[2]=b.x; d_keys[3]=b.y;
    }
}

__global__ void k_xg(const float* __restrict__ Wf,const float* __restrict__ bif,
                     const float* __restrict__ bhf,const float* __restrict__ Wb,
                     const float* __restrict__ bib,const float* __restrict__ bhb){
    int dir=blockIdx.y, j0=blockIdx.x*16, t=threadIdx.x;
    const float* W = dir?Wb:Wf; const float* b1=dir?bib:bif; const float* b2=dir?bhb:bhf;
    __shared__ float Ws[16][ED]; __shared__ float bs[16];
    for(int i=t;i<16*ED;i+=128) Ws[i>>8][i&255]=W[(size_t)(j0+(i>>8))*ED+(i&255)];
    if(t<16) bs[t]=b1[j0+t]+b2[j0+t];
    __syncthreads();
    int ts = dir?(127-t):t;
    float acc[16];
#pragma unroll
    for(int c=0;c<16;c++) acc[c]=0.0f;
    for(int k=0;k<ED;k++){
        float xv=d_xT[k*NT1+ts];
#pragma unroll
        for(int c=0;c<16;c++) acc[c]=fmaf(xv,Ws[c][k],acc[c]);
    }
#pragma unroll
    for(int c=0;c<16;c++) d_xg[(size_t)(dir*NT1+t)*G4+j0+c]=acc[c]+bs[c];
}

// blocks 0..63: persistent bi-LSTM (tagged-word sync). blocks 64..: fp32->bf16 weight convert.
__global__ void __launch_bounds__(512,1) k_lstm(const float* __restrict__ Whf,
                                                const float* __restrict__ Whb,
                                                const float* __restrict__ fWp,
                                                const float* __restrict__ gWp){
    int bid=blockIdx.x, tid=threadIdx.x;
    if(bid>=64){
        const float4* f4=(const float4*)fWp;
        const float4* g4=(const float4*)gWp;
        const size_t TOT=(size_t)VV*HD/4;
        for(size_t idx=(size_t)(bid-64)*512+tid; idx<TOT; idx+=(size_t)CVB*512){
            float4 a=f4[idx];
            __nv_bfloat162* o=(__nv_bfloat162*)(d_fWb+idx*4);
            o[0]=__floats2bfloat162_rn(a.x,a.y); o[1]=__floats2bfloat162_rn(a.z,a.w);
            float4 b=g4[idx];
            __nv_bfloat162* o2=(__nv_bfloat162*)(d_gWb+idx*4);
            o2[0]=__floats2bfloat162_rn(b.x,b.y); o2[1]=__floats2bfloat162_rn(b.z,b.w);
        }
        return;
    }
    int dir=bid>>5, blk=bid&31, j0=blk*16;
    int wp=tid>>5, l=tid&31, g=l>>3, seg=l&7;
    int j=j0+wp;
    const float* Whh = dir?Whb:Whf;
    float w[64];
    {
        const float* wr=Whh+(size_t)(g*HD+j)*HD+seg;
#pragma unroll
        for(int ii=0;ii<64;ii++) w[ii]=wr[ii*8];
    }
    __shared__ float hs[HD];
    __shared__ float xgs[NT1*64];
    for(int idx=tid; idx<NT1*64; idx+=512){
        int s=idx>>6, r=idx&63, gg=r>>4, uu=r&15;
        xgs[idx]=d_xg[(size_t)(dir*NT1+s)*G4 + gg*HD + j0+uu];
    }
    float c=0.0f;
    u64* buf0=&d_hb64[dir*2*HD];
    __syncthreads();
    for(int s=0;s<NT1;s++){
        const u64* pw=&buf0[(s&1)*HD + tid];
        u32 got=0; float hv=0.0f;
        do{
            if(!got){
                u64 v=__ldcg(pw);
                if((u32)(v>>32)>=(u32)s){ hv=__uint_as_float((u32)v); got=1; }
            }
        }while(!__all_sync(0xffffffffu,got));
        hs[tid]=hv;
        __syncthreads();
        float p0=0.f,p1=0.f,p2=0.f,p3=0.f;
        const float* hb=hs+seg;
#pragma unroll
        for(int ii=0;ii<64;ii+=4){
            p0=fmaf(w[ii],  hb[ii*8],    p0);
            p1=fmaf(w[ii+1],hb[ii*8+8],  p1);
            p2=fmaf(w[ii+2],hb[ii*8+16], p2);
            p3=fmaf(w[ii+3],hb[ii*8+24], p3);
        }
        float p=(p0+p1)+(p2+p3);
        p+=__shfl_xor_sync(~0u,p,1); p+=__shfl_xor_sync(~0u,p,2); p+=__shfl_xor_sync(~0u,p,4);
        float val=p+xgs[s*64+g*16+wp];
        float gi=__shfl_sync(~0u,val,0),  gf=__shfl_sync(~0u,val,8);
        float gg2=__shfl_sync(~0u,val,16),go=__shfl_sync(~0u,val,24);
        c=fsig(gf)*c+fsig(gi)*ftanh(gg2);
        float h=fsig(go)*ftanh(c);
        if(l==0){
            u64 pk=(((u64)(u32)(s+1))<<32)|(u64)__float_as_uint(h);
            __stcg(&buf0[((s+1)&1)*HD + j], pk);
            int tt=dir?(127-s):s;
            __stcg(&d_hcat[(size_t)tt*(2*HD)+dir*HD+j],h);
        }
        __syncthreads();
    }
}

__global__ void k_us(const float* __restrict__ UW,const float* __restrict__ Ub,
                     const float* __restrict__ SW,const float* __restrict__ Sb){
    int jt=blockIdx.x, m=blockIdx.y, j0=jt*8, t=threadIdx.x;
    const float* W=m?SW:UW; const float* bb=m?Sb:Ub;
    __shared__ float Wt[8][2*HD];
    const float4* Wv=(const float4*)(W+(size_t)j0*2*HD);
    float4* Ws=(float4*)Wt;
    for(int i=t;i<8*2*HD/4;i+=128) Ws[i]=Wv[i];
    __syncthreads();
    float acc[8];
#pragma unroll
    for(int cc=0;cc<8;cc++) acc[cc]=0.0f;
    const float4* h4=(const float4*)&d_hcat[(size_t)t*2*HD];
    for(int k=0;k<2*HD/4;k++){
        float4 hv=h4[k];
#pragma unroll
        for(int cc=0;cc<8;cc++){
            float4 wv=*(const float4*)&Wt[cc][k*4];
            acc[cc]=fmaf(hv.x,wv.x,fmaf(hv.y,wv.y,fmaf(hv.z,wv.z,fmaf(hv.w,wv.w,acc[cc]))));
        }
    }
#pragma unroll
    for(int cc=0;cc<8;cc++){
        float x=acc[cc]+bb[j0+cc];
        if(m) d_s[t*HD+j0+cc]=log1pf(expf(-fabsf(x)))+fmaxf(x,0.0f);
        else  d_u[t*HD+j0+cc]=x;
    }
}

__global__ void k_sample(){
    int r=blockIdx.x, j=threadIdx.x;
    int t = (r<128)? r : ((r-128)&127);
    u32 k0,k1; unsigned flat;
    if(r<128){ k0=d_keys[0]; k1=d_keys[1]; flat=(unsigned)(r*HD+j); }
    else     { k0=d_keys[2]; k1=d_keys[3]; flat=(unsigned)((r-128)*HD+j); }
    uint2 o=tf2x32(k0,k1,0u,flat);
    float n=jnormal(o.x^o.y);
    float uu=d_u[t*HD+j], ss=d_s[t*HD+j];
    d_zb[(size_t)r*HD+j]=__float2bfloat16_rn(uu+ss*n);
    if(r<128){
        float v=0.5f*(ss*ss+uu*uu-1.0f-2.0f*logf(ss));
#pragma unroll
        for(int o2=16;o2;o2>>=1) v+=__shfl_xor_sync(~0u,v,o2);
        __shared__ float sw[16];
        if((j&31)==0) sw[j>>5]=v;
        __syncthreads();
        if(j<16){ v=sw[j];
            for(int o2=8;o2;o2>>=1) v+=__shfl_xor_sync(0xffffu,v,o2);
            if(j==0) atomicAdd(&d_kl,v);
        }
    }
}

// bf16 mma.sync GEMM, cp.async double-buffered, ldmatrix fragments,
// fused bias + online log-softmax partials.
__global__ void __launch_bounds__(256) k_mma(const float* __restrict__ fb,const float* __restrict__ gb,
        const int* __restrict__ wl1,const int* __restrict__ wl2){
    extern __shared__ char dyn[];
    __nv_bfloat16* As=(__nv_bfloat16*)(dyn+SM_A);
    __nv_bfloat16* Bs=(__nv_bfloat16*)(dyn+SM_B);
    float* sbias=(float*)(dyn+SM_BIAS);
    float (*red_m)[4]=(float(*)[4])(dyn+SM_RM);
    float (*red_s)[4]=(float(*)[4])(dyn+SM_RS);
    int tid=threadIdx.x, cx=blockIdx.x, ry=blockIdx.y;
    int col0=cx*128, row0=ry*128;
    const __nv_bfloat16* Wsrc = ry? d_gWb : d_fWb;
    const float* bb = ry? gb : fb;
    if(tid<128) sbias[tid]=bb[col0+tid];
    int lane=tid&31, warp=tid>>5, rw=warp>>2, cw=warp&3;
    float acc[4][4][4];
#pragma unroll
    for(int mt=0;mt<4;mt++)
#pragma unroll
        for(int nt=0;nt<4;nt++)
#pragma unroll
            for(int q=0;q<4;q++) acc[mt][nt][q]=0.0f;
    int lr=tid>>1, half=(tid&1);
    u32 asb=s2u(As), bsb=s2u(Bs);
    const __nv_bfloat16* gA=d_zb+(size_t)(row0+lr)*HD;
    const __nv_bfloat16* gB=Wsrc+(size_t)(col0+lr)*HD;
    u32 soff=(u32)(lr*144+half*64);
    // ldmatrix lane addresses (relative to stage base)
    u32 aoff=(u32)((rw*64+(lane&15))*144 + ((lane>>4)&1)*16);
    u32 boff=(u32)((cw*32+((lane>>4)&1)*8+(lane&7))*144 + ((lane>>3)&1)*16);
#define PREFETCH(ch) { u32 bsel=(u32)(((ch)&1)*STAGE_B); \
    const __nv_bfloat16* ga=gA+(ch)*64+half*32; \
    const __nv_bfloat16* gbp=gB+(ch)*64+half*32; \
    _Pragma("unroll") for(int i=0;i<4;i++){ \
        cpa16(asb+bsel+soff+i*16, ga+i*8); \
        cpa16(bsb+bsel+soff+i*16, gbp+i*8); } \
    asm volatile("cp.async.commit_group;":::"memory"); }
    PREFETCH(0)
    for(int ch=0;ch<8;ch++){
        if(ch<7){ PREFETCH(ch+1) asm volatile("cp.async.wait_group 1;":::"memory"); }
        else    { asm volatile("cp.async.wait_group 0;":::"memory"); }
        __syncthreads();
        u32 stage=(u32)((ch&1)*STAGE_B);
        u32 aab=asb+stage+aoff;
        u32 bb0=bsb+stage+boff;
#pragma unroll
        for(int ks=0;ks<4;ks++){
            u32 a[4][4], b2[4][2];
#pragma unroll
            for(int mt=0;mt<4;mt++)
                ldsm4(a[mt][0],a[mt][1],a[mt][2],a[mt][3], aab+mt*16*144+ks*32);
            ldsm4(b2[0][0],b2[0][1],b2[1][0],b2[1][1], bb0+ks*32);
            ldsm4(b2[2][0],b2[2][1],b2[3][0],b2[3][1], bb0+16*144+ks*32);
#pragma unroll
            for(int mt=0;mt<4;mt++)
#pragma unroll
                for(int nt=0;nt<4;nt++)
                    asm volatile("mma.sync.aligned.m16n8k16.row.col.f32.bf16.bf16.f32 "
                        "{%0,%1,%2,%3},{%4,%5,%6,%7},{%8,%9},{%0,%1,%2,%3};"
                        :"+f"(acc[mt][nt][0]),"+f"(acc[mt][nt][1]),"+f"(acc[mt][nt][2]),"+f"(acc[mt][nt][3])
                        :"r"(a[mt][0]),"r"(a[mt][1]),"r"(a[mt][2]),"r"(a[mt][3]),
                         "r"(b2[nt][0]),"r"(b2[nt][1]));
        }
        __syncthreads();
    }
#pragma unroll
    for(int mt=0;mt<4;mt++)
#pragma unroll
        for(int nt=0;nt<4;nt++){
            float b0=sbias[cw*32+nt*8+(lane&3)*2], b1=sbias[cw*32+nt*8+(lane&3)*2+1];
            acc[mt][nt][0]+=b0; acc[mt][nt][1]+=b1;
            acc[mt][nt][2]+=b0; acc[mt][nt][3]+=b1;
        }
#pragma unroll
    for(int mt=0;mt<4;mt++)
#pragma unroll
        for(int h=0;h<2;h++){
            float m=-1e30f;
#pragma unroll
            for(int nt=0;nt<4;nt++) m=fmaxf(m,fmaxf(acc[mt][nt][h*2],acc[mt][nt][h*2+1]));
            m=fmaxf(m,__shfl_xor_sync(~0u,m,1));
            m=fmaxf(m,__shfl_xor_sync(~0u,m,2));
            if((lane&3)==0) red_m[rw*64+mt*16+(lane>>2)+h*8][cw]=m;
        }
    __syncthreads();
#pragma unroll
    for(int mt=0;mt<4;mt++)
#pragma unroll
        for(int h=0;h<2;h++){
            int rloc=rw*64+mt*16+(lane>>2)+h*8;
            int rg=row0+rloc;
            float M=fmaxf(fmaxf(red_m[rloc][0],red_m[rloc][1]),fmaxf(red_m[rloc][2],red_m[rloc][3]));
            int tw=(rg<128)?wl1[rg]:wl2[(rg-128)>>7];
            int tloc=tw-col0;
            float s=0.0f;
#pragma unroll
            for(int nt=0;nt<4;nt++){
                int c0=cw*32+nt*8+(lane&3)*2;
                float v0=acc[mt][nt][h*2], v1=acc[mt][nt][h*2+1];
                if(c0==tloc)   d_tgt[rg]=v0;
                if(c0+1==tloc) d_tgt[rg]=v1;
                s+=__expf(v0-M)+__expf(v1-M);
            }
            s+=__shfl_xor_sync(~0u,s,1);
            s+=__shfl_xor_sync(~0u,s,2);
            if((lane&3)==0) red_s[rloc][cw]=s;
        }
    __syncthreads();
    if(tid<128){
        float M=fmaxf(fmaxf(red_m[tid][0],red_m[tid][1]),fmaxf(red_m[tid][2],red_m[tid][3]));
        float S=red_s[tid][0]+red_s[tid][1]+red_s[tid][2]+red_s[tid][3];
        int rg=row0+tid;
        d_pm[(size_t)rg*NCT+cx]=M;
        d_ps[(size_t)rg*NCT+cx]=S;
    }
}

__global__ void k_final(){
    int r=blockIdx.x, tid=threadIdx.x;
    __shared__ float sw[4]; __shared__ float sM;
    float M=-1e30f;
    for(int i=tid;i<NCT;i+=128) M=fmaxf(M,d_pm[(size_t)r*NCT+i]);
    for(int o=16;o;o>>=1) M=fmaxf(M,__shfl_xor_sync(~0u,M,o));
    if((tid&31)==0) sw[tid>>5]=M;
    __syncthreads();
    if(tid==0) sM=fmaxf(fmaxf(sw[0],sw[1]),fmaxf(sw[2],sw[3]));
    __syncthreads();
    float Mf=sM, S=0.0f;
    for(int i=tid;i<NCT;i+=128) S+=d_ps[(size_t)r*NCT+i]*expf(d_pm[(size_t)r*NCT+i]-Mf);
    for(int o=16;o;o>>=1) S+=__shfl_xor_sync(~0u,S,o);
    if((tid&31)==0) sw[tid>>5]=S;
    __syncthreads();
    if(tid==0){
        S=sw[0]+sw[1]+sw[2]+sw[3];
        float lp=d_tgt[r]-(logf(S)+Mf);
        float wg=(r<128)?1.0f:(1.0f/16.0f);
        atomicAdd(&d_acc,lp*wg);
    }
}

__global__ void k_out(float* out){ out[0]=-d_kl+d_acc; }

extern "C" void kernel_launch(void* const* d_in, const int* in_sizes, int n_in,
                              void* d_out, int out_size){
    const int*   wl1=(const int*)d_in[0];
    const int*   wl2=(const int*)d_in[1];
    const float* emb=(const float*)d_in[2];
    const float* Wihf=(const float*)d_in[3];
    const float* Whhf=(const float*)d_in[4];
    const float* bihf=(const float*)d_in[5];
    const float* bhhf=(const float*)d_in[6];
    const float* Wihb=(const float*)d_in[7];
    const float* Whhb=(const float*)d_in[8];
    const float* bihb=(const float*)d_in[9];
    const float* bhhb=(const float*)d_in[10];
    const float* UW=(const float*)d_in[11];
    const float* Ub=(const float*)d_in[12];
    const float* SW=(const float*)d_in[13];
    const float* Sb=(const float*)d_in[14];
    const float* fW=(const float*)d_in[15];
    const float* fb=(const float*)d_in[16];
    const float* gW=(const float*)d_in[17];
    const float* gb=(const float*)d_in[18];
    cudaFuncSetAttribute(k_mma, cudaFuncAttributeMaxDynamicSharedMemorySize, SM_TOT);
    k_init<<<256,128>>>(wl1,emb);
    k_xg<<<dim3(128,2),128>>>(Wihf,bihf,bhhf,Wihb,bihb,bhhb);
    k_lstm<<<64+CVB,512>>>(Whhf,Whhb,fW,gW);
    k_us<<<dim3(64,2),128>>>(UW,Ub,SW,Sb);
    k_sample<<<RTOT,512>>>();
    k_mma<<<dim3(NCT,17),256,SM_TOT>>>(fb,gb,wl1,wl2);
    k_final<<<RTOT,128>>>();
    k_out<<<1,1>>>((float*)d_out);
}

// round 12
// speedup vs baseline: 2.0419x; 1.0779x over previous
#include <cuda_runtime.h>
#include <cuda_bf16.h>
typedef unsigned int u32; typedef unsigned long long u64;

#define NT1 128
#define ED  256
#define HD  512
#define G4  2048
#define RTOT 2176
#define NCT 250
#define VV  32000
#define STG 36864
#define SM_TOT 110592
#define CVB 1024

__device__ float d_xT[ED*NT1];
__device__ float d_xg[2*NT1*G4];
__device__ u64  d_hb64[2*2*HD];
__device__ float d_hcat[NT1*2*HD];
__device__ float d_u[NT1*HD];
__device__ float d_s[NT1*HD];
__device__ __align__(16) __nv_bfloat16 d_zb[(size_t)RTOT*HD];
__device__ __align__(16) __nv_bfloat16 d_fWb[(size_t)VV*HD];
__device__ __align__(16) __nv_bfloat16 d_gWb[(size_t)VV*HD];
__device__ float d_pm[(size_t)RTOT*NCT];
__device__ float d_ps[(size_t)RTOT*NCT];
__device__ float d_tgt[RTOT];
__device__ u32 d_keys[4];
__device__ int d_cnt;
__device__ float d_kl, d_acc;

__device__ __forceinline__ uint2 tf2x32(u32 k0,u32 k1,u32 c0,u32 c1){
    u32 ks2=0x1BD11BDAu^k0^k1, x0=c0+k0, x1=c1+k1;
#define TFR(r) {x0+=x1; x1=__funnelshift_l(x1,x1,r); x1^=x0;}
    TFR(13)TFR(15)TFR(26)TFR(6)  x0+=k1;  x1+=ks2+1u;
    TFR(17)TFR(29)TFR(16)TFR(24) x0+=ks2; x1+=k0+2u;
    TFR(13)TFR(15)TFR(26)TFR(6)  x0+=k0;  x1+=k1+3u;
    TFR(17)TFR(29)TFR(16)TFR(24) x0+=k1;  x1+=ks2+4u;
    TFR(13)TFR(15)TFR(26)TFR(6)  x0+=ks2; x1+=k0+5u;
#undef TFR
    return make_uint2(x0,x1);
}
__device__ __forceinline__ float jnormal(u32 bits){
    float f=__uint_as_float((bits>>9)|0x3f800000u)-1.0f;
    const float lo=__int_as_float(0xBF7FFFFF);
    float u=fmaxf(lo, f*(1.0f-lo)+lo);
    float w=-log1pf(-u*u), p;
    if(w<5.0f){ w-=2.5f;
        p=2.81022636e-08f;           p=fmaf(p,w,3.43273939e-07f);
        p=fmaf(p,w,-3.5233877e-06f); p=fmaf(p,w,-4.39150654e-06f);
        p=fmaf(p,w,0.00021858087f);  p=fmaf(p,w,-0.00125372503f);
        p=fmaf(p,w,-0.00417768164f); p=fmaf(p,w,0.246640727f);
        p=fmaf(p,w,1.50140941f);
    } else { w=sqrtf(w)-3.0f;
        p=-0.000200214257f;          p=fmaf(p,w,0.000100950558f);
        p=fmaf(p,w,0.00134934322f);  p=fmaf(p,w,-0.00367342844f);
        p=fmaf(p,w,0.00573950773f);  p=fmaf(p,w,-0.0076224613f);
        p=fmaf(p,w,0.00943887047f);  p=fmaf(p,w,1.00167406f);
        p=fmaf(p,w,2.83297682f);
    }
    return 1.41421354f*(p*u);
}
__device__ __forceinline__ float fsig(float x){ return __fdividef(1.0f,1.0f+__expf(-x)); }
__device__ __forceinline__ float ftanh(float x){ return 1.0f-__fdividef(2.0f,__expf(2.0f*x)+1.0f); }
__device__ __forceinline__ u32 s2u(const void* p){
    u32 a; asm("{ .reg .u64 t; cvta.to.shared.u64 t, %1; cvt.u32.u64 %0, t; }":"=r"(a):"l"(p)); return a;
}
__device__ __forceinline__ void cpa16(u32 d,const void* s){
    asm volatile("cp.async.cg.shared.global [%0],[%1],16;"::"r"(d),"l"(s):"memory");
}
__device__ __forceinline__ void ldsm4(u32& r0,u32& r1,u32& r2,u32& r3,u32 a){
    asm volatile("ldmatrix.sync.aligned.m8n8.x4.shared.b16 {%0,%1,%2,%3},[%4];"
        :"=r"(r0),"=r"(r1),"=r"(r2),"=r"(r3):"r"(a));
}

__global__ void k_init(const int* __restrict__ wl1, const float* __restrict__ emb){
    int tid=blockIdx.x*blockDim.x+threadIdx.x;
    int t=tid&127, k=tid>>7;
    d_xT[k*NT1+t]=emb[(size_t)wl1[t]*ED+k];
    if(tid<2048) d_hb64[tid]=0ull;
    if(tid==0){
        d_kl=0.0f; d_acc=0.0f; d_cnt=0;
        uint2 a=tf2x32(0u,42u,0u,0u), b=tf2x32(0u,42u,0u,1u);
        d_keys[0]=a.x; d_keys[1]=a.y; d_keys[2]=b.x; d_keys[3]=b.y;
    }
}

__global__ void k_xg(const float* __restrict__ Wf,const float* __restrict__ bif,
                     const float* __restrict__ bhf,const float* __restrict__ Wb,
                     const float* __restrict__ bib,const float* __restrict__ bhb){
    int dir=blockIdx.y, j0=blockIdx.x*16, t=threadIdx.x;
    const float* W = dir?Wb:Wf; const float* b1=dir?bib:bif; const float* b2=dir?bhb:bhf;
    __shared__ float Ws[16][ED]; __shared__ float bs[16];
    for(int i=t;i<16*ED;i+=128) Ws[i>>8][i&255]=W[(size_t)(j0+(i>>8))*ED+(i&255)];
    if(t<16) bs[t]=b1[j0+t]+b2[j0+t];
    __syncthreads();
    int ts = dir?(127-t):t;
    float acc[16];
#pragma unroll
    for(int c=0;c<16;c++) acc[c]=0.0f;
    for(int k=0;k<ED;k++){
        float xv=d_xT[k*NT1+ts];
#pragma unroll
        for(int c=0;c<16;c++) acc[c]=fmaf(xv,Ws[c][k],acc[c]);
    }
#pragma unroll
    for(int c=0;c<16;c++) d_xg[(size_t)(dir*NT1+t)*G4+j0+c]=acc[c]+bs[c];
}

// blocks 0..63: persistent bi-LSTM (tagged-word sync). blocks 64..: fp32->bf16 weight convert.
__global__ void __launch_bounds__(512,1) k_lstm(const float* __restrict__ Whf,
                                                const float* __restrict__ Whb,
                                                const float* __restrict__ fWp,
                                                const float* __restrict__ gWp){
    int bid=blockIdx.x, tid=threadIdx.x;
    if(bid>=64){
        const float4* f4=(const float4*)fWp;
        const float4* g4=(const float4*)gWp;
        const size_t TOT=(size_t)VV*HD/4;
        for(size_t idx=(size_t)(bid-64)*512+tid; idx<TOT; idx+=(size_t)CVB*512){
            float4 a=f4[idx];
            __nv_bfloat162* o=(__nv_bfloat162*)(d_fWb+idx*4);
            o[0]=__floats2bfloat162_rn(a.x,a.y); o[1]=__floats2bfloat162_rn(a.z,a.w);
            float4 b=g4[idx];
            __nv_bfloat162* o2=(__nv_bfloat162*)(d_gWb+idx*4);
            o2[0]=__floats2bfloat162_rn(b.x,b.y); o2[1]=__floats2bfloat162_rn(b.z,b.w);
        }
        return;
    }
    int dir=bid>>5, blk=bid&31, j0=blk*16;
    int wp=tid>>5, l=tid&31, g=l>>3, seg=l&7;
    int j=j0+wp;
    const float* Whh = dir?Whb:Whf;
    float w[64];
    {
        const float* wr=Whh+(size_t)(g*HD+j)*HD+seg;
#pragma unroll
        for(int ii=0;ii<64;ii++) w[ii]=wr[ii*8];
    }
    __shared__ float hs[HD];
    __shared__ float xgs[NT1*64];
    for(int idx=tid; idx<NT1*64; idx+=512){
        int s=idx>>6, r=idx&63, gg=r>>4, uu=r&15;
        xgs[idx]=d_xg[(size_t)(dir*NT1+s)*G4 + gg*HD + j0+uu];
    }
    float c=0.0f;
    u64* buf0=&d_hb64[dir*2*HD];
    __syncthreads();
    for(int s=0;s<NT1;s++){
        const u64* pw=&buf0[(s&1)*HD + tid];
        u32 got=0; float hv=0.0f;
        do{
            if(!got){
                u64 v=__ldcg(pw);
                if((u32)(v>>32)>=(u32)s){ hv=__uint_as_float((u32)v); got=1; }
            }
        }while(!__all_sync(0xffffffffu,got));
        hs[tid]=hv;
        __syncthreads();
        float p0=0.f,p1=0.f,p2=0.f,p3=0.f;
        const float* hb=hs+seg;
#pragma unroll
        for(int ii=0;ii<64;ii+=4){
            p0=fmaf(w[ii],  hb[ii*8],    p0);
            p1=fmaf(w[ii+1],hb[ii*8+8],  p1);
            p2=fmaf(w[ii+2],hb[ii*8+16], p2);
            p3=fmaf(w[ii+3],hb[ii*8+24], p3);
        }
        float p=(p0+p1)+(p2+p3);
        p+=__shfl_xor_sync(~0u,p,1); p+=__shfl_xor_sync(~0u,p,2); p+=__shfl_xor_sync(~0u,p,4);
        float val=p+xgs[s*64+g*16+wp];
        float gi=__shfl_sync(~0u,val,0),  gf=__shfl_sync(~0u,val,8);
        float gg2=__shfl_sync(~0u,val,16),go=__shfl_sync(~0u,val,24);
        c=fsig(gf)*c+fsig(gi)*ftanh(gg2);
        float h=fsig(go)*ftanh(c);
        if(l==0){
            u64 pk=(((u64)(u32)(s+1))<<32)|(u64)__float_as_uint(h);
            __stcg(&buf0[((s+1)&1)*HD + j], pk);
            int tt=dir?(127-s):s;
            __stcg(&d_hcat[(size_t)tt*(2*HD)+dir*HD+j],h);
        }
        __syncthreads();
    }
}

// split-k u/s heads: 2 threads per token, halved dependency chain.
__global__ void __launch_bounds__(256) k_us(const float* __restrict__ UW,const float* __restrict__ Ub,
                     const float* __restrict__ SW,const float* __restrict__ Sb){
    int jt=blockIdx.x, m=blockIdx.y, j0=jt*8;
    int tid=threadIdx.x, tk=tid&1, t=tid>>1;
    const float* W=m?SW:UW; const float* bb=m?Sb:Ub;
    __shared__ float Wt[8][2*HD];
    const float4* Wv=(const float4*)(W+(size_t)j0*2*HD);
    float4* Ws=(float4*)Wt;
    for(int i=tid;i<8*2*HD/4;i+=256) Ws[i]=Wv[i];
    __syncthreads();
    float acc[8];
#pragma unroll
    for(int cc=0;cc<8;cc++) acc[cc]=0.0f;
    const float4* h4=(const float4*)&d_hcat[(size_t)t*2*HD] + tk*128;
#pragma unroll 4
    for(int k=0;k<128;k++){
        float4 hv=h4[k];
#pragma unroll
        for(int cc=0;cc<8;cc++){
            float4 wv=*((const float4*)&Wt[cc][0] + tk*128 + k);
            acc[cc]=fmaf(hv.x,wv.x,fmaf(hv.y,wv.y,fmaf(hv.z,wv.z,fmaf(hv.w,wv.w,acc[cc]))));
        }
    }
#pragma unroll
    for(int cc=0;cc<8;cc++) acc[cc]+=__shfl_xor_sync(~0u,acc[cc],1);
    if(tk==0){
#pragma unroll
        for(int cc=0;cc<8;cc++){
            float x=acc[cc]+bb[j0+cc];
            if(m) d_s[t*HD+j0+cc]=log1pf(expf(-fabsf(x)))+fmaxf(x,0.0f);
            else  d_u[t*HD+j0+cc]=x;
        }
    }
}

__global__ void k_sample(){
    int r=blockIdx.x, j=threadIdx.x;
    int t = (r<128)? r : ((r-128)&127);
    u32 k0,k1; unsigned flat;
    if(r<128){ k0=d_keys[0]; k1=d_keys[1]; flat=(unsigned)(r*HD+j); }
    else     { k0=d_keys[2]; k1=d_keys[3]; flat=(unsigned)((r-128)*HD+j); }
    uint2 o=tf2x32(k0,k1,0u,flat);
    float n=jnormal(o.x^o.y);
    float uu=d_u[t*HD+j], ss=d_s[t*HD+j];
    d_zb[(size_t)r*HD+j]=__float2bfloat16_rn(uu+ss*n);
    if(r<128){
        float v=0.5f*(ss*ss+uu*uu-1.0f-2.0f*logf(ss));
#pragma unroll
        for(int o2=16;o2;o2>>=1) v+=__shfl_xor_sync(~0u,v,o2);
        __shared__ float sw[16];
        if((j&31)==0) sw[j>>5]=v;
        __syncthreads();
        if(j<16){ v=sw[j];
            for(int o2=8;o2;o2>>=1) v+=__shfl_xor_sync(0xffffu,v,o2);
            if(j==0) atomicAdd(&d_kl,v);
        }
    }
}

// bf16 mma.sync GEMM: 3-stage cp.async pipeline, ldmatrix fragments, one sync/chunk,
// bias+reduction arrays overlaid on stage buffers after the mainloop.
__global__ void __launch_bounds__(256) k_mma(const float* __restrict__ fb,const float* __restrict__ gb,
        const int* __restrict__ wl1,const int* __restrict__ wl2){
    extern __shared__ char dyn[];
    int tid=threadIdx.x, cx=blockIdx.x, ry=blockIdx.y;
    int col0=cx*128, row0=ry*128;
    const __nv_bfloat16* Wsrc = ry? d_gWb : d_fWb;
    const float* bb = ry? gb : fb;
    int lane=tid&31, warp=tid>>5, rw=warp>>2, cw=warp&3;
    float acc[4][4][4];
#pragma unroll
    for(int mt=0;mt<4;mt++)
#pragma unroll
        for(int nt=0;nt<4;nt++)
#pragma unroll
            for(int q=0;q<4;q++) acc[mt][nt][q]=0.0f;
    int lr=tid>>1, half=(tid&1);
    u32 dybase=s2u(dyn);
    const __nv_bfloat16* gA=d_zb+(size_t)(row0+lr)*HD;
    const __nv_bfloat16* gB=Wsrc+(size_t)(col0+lr)*HD;
    u32 soff=(u32)(lr*144+half*64);
    u32 aoff=(u32)((rw*64+(lane&15))*144 + ((lane>>4)&1)*16);
    u32 boff=(u32)(18432 + (cw*32+((lane>>4)&1)*8+(lane&7))*144 + ((lane>>3)&1)*16);
#define PREFETCH(ch) { u32 bsel=dybase+(u32)(((ch)%3)*STG); \
    const __nv_bfloat16* ga=gA+(ch)*64+half*32; \
    const __nv_bfloat16* gbp=gB+(ch)*64+half*32; \
    _Pragma("unroll") for(int i=0;i<4;i++){ \
        cpa16(bsel+soff+i*16, ga+i*8); \
        cpa16(bsel+18432u+soff+i*16, gbp+i*8); } \
    asm volatile("cp.async.commit_group;":::"memory"); }
    PREFETCH(0)
    PREFETCH(1)
    for(int ch=0;ch<8;ch++){
        if(ch<7) asm volatile("cp.async.wait_group 1;":::"memory");
        else     asm volatile("cp.async.wait_group 0;":::"memory");
        __syncthreads();
        if(ch<6) PREFETCH(ch+2)
        u32 stage=dybase+(u32)((ch%3)*STG);
        u32 aab=stage+aoff;
        u32 bb0=stage+boff;
#pragma unroll
        for(int ks=0;ks<4;ks++){
            u32 a[4][4], b2[4][2];
#pragma unroll
            for(int mt=0;mt<4;mt++)
                ldsm4(a[mt][0],a[mt][1],a[mt][2],a[mt][3], aab+mt*16*144+ks*32);
            ldsm4(b2[0][0],b2[0][1],b2[1][0],b2[1][1], bb0+ks*32);
            ldsm4(b2[2][0],b2[2][1],b2[3][0],b2[3][1], bb0+16*144+ks*32);
#pragma unroll
            for(int mt=0;mt<4;mt++)
#pragma unroll
                for(int nt=0;nt<4;nt++)
                    asm volatile("mma.sync.aligned.m16n8k16.row.col.f32.bf16.bf16.f32 "
                        "{%0,%1,%2,%3},{%4,%5,%6,%7},{%8,%9},{%0,%1,%2,%3};"
                        :"+f"(acc[mt][nt][0]),"+f"(acc[mt][nt][1]),"+f"(acc[mt][nt][2]),"+f"(acc[mt][nt][3])
                        :"r"(a[mt][0]),"r"(a[mt][1]),"r"(a[mt][2]),"r"(a[mt][3]),
                         "r"(b2[nt][0]),"r"(b2[nt][1]));
        }
        __syncthreads();
    }
    // overlay scratch on stage buffers (mainloop done for all warps after last sync)
    float* sbias=(float*)dyn;
    float (*red_m)[4]=(float(*)[4])(dyn+512);
    float (*red_s)[4]=(float(*)[4])(dyn+2560);
    if(tid<128) sbias[tid]=bb[col0+tid];
    __syncthreads();
#pragma unroll
    for(int mt=0;mt<4;mt++)
#pragma unroll
        for(int nt=0;nt<4;nt++){
            float b0=sbias[cw*32+nt*8+(lane&3)*2], b1=sbias[cw*32+nt*8+(lane&3)*2+1];
            acc[mt][nt][0]+=b0; acc[mt][nt][1]+=b1;
            acc[mt][nt][2]+=b0; acc[mt][nt][3]+=b1;
        }
#pragma unroll
    for(int mt=0;mt<4;mt++)
#pragma unroll
        for(int h=0;h<2;h++){
            float m=-1e30f;
#pragma unroll
            for(int nt=0;nt<4;nt++) m=fmaxf(m,fmaxf(acc[mt][nt][h*2],acc[mt][nt][h*2+1]));
            m=fmaxf(m,__shfl_xor_sync(~0u,m,1));
            m=fmaxf(m,__shfl_xor_sync(~0u,m,2));
            if((lane&3)==0) red_m[rw*64+mt*16+(lane>>2)+h*8][cw]=m;
        }
    __syncthreads();
#pragma unroll
    for(int mt=0;mt<4;mt++)
#pragma unroll
        for(int h=0;h<2;h++){
            int rloc=rw*64+mt*16+(lane>>2)+h*8;
            int rg=row0+rloc;
            float M=fmaxf(fmaxf(red_m[rloc][0],red_m[rloc][1]),fmaxf(red_m[rloc][2],red_m[rloc][3]));
            int tw=(rg<128)?wl1[rg]:wl2[(rg-128)>>7];
            int tloc=tw-col0;
            float s=0.0f;
#pragma unroll
            for(int nt=0;nt<4;nt++){
                int c0=cw*32+nt*8+(lane&3)*2;
                float v0=acc[mt][nt][h*2], v1=acc[mt][nt][h*2+1];
                if(c0==tloc)   d_tgt[rg]=v0;
                if(c0+1==tloc) d_tgt[rg]=v1;
                s+=__expf(v0-M)+__expf(v1-M);
            }
            s+=__shfl_xor_sync(~0u,s,1);
            s+=__shfl_xor_sync(~0u,s,2);
            if((lane&3)==0) red_s[rloc][cw]=s;
        }
    __syncthreads();
    if(tid<128){
        float M=fmaxf(fmaxf(red_m[tid][0],red_m[tid][1]),fmaxf(red_m[tid][2],red_m[tid][3]));
        float S=red_s[tid][0]+red_s[tid][1]+red_s[tid][2]+red_s[tid][3];
        int rg=row0+tid;
        d_pm[(size_t)rg*NCT+cx]=M;
        d_ps[(size_t)rg*NCT+cx]=S;
    }
}

__global__ void k_final(float* __restrict__ out){
    int r=blockIdx.x, tid=threadIdx.x;
    __shared__ float sw[4]; __shared__ float sM;
    float M=-1e30f;
    for(int i=tid;i<NCT;i+=128) M=fmaxf(M,d_pm[(size_t)r*NCT+i]);
    for(int o=16;o;o>>=1) M=fmaxf(M,__shfl_xor_sync(~0u,M,o));
    if((tid&31)==0) sw[tid>>5]=M;
    __syncthreads();
    if(tid==0) sM=fmaxf(fmaxf(sw[0],sw[1]),fmaxf(sw[2],sw[3]));
    __syncthreads();
    float Mf=sM, S=0.0f;
    for(int i=tid;i<NCT;i+=128) S+=d_ps[(size_t)r*NCT+i]*expf(d_pm[(size_t)r*NCT+i]-Mf);
    for(int o=16;o;o>>=1) S+=__shfl_xor_sync(~0u,S,o);
    if((tid&31)==0) sw[tid>>5]=S;
    __syncthreads();
    if(tid==0){
        S=sw[0]+sw[1]+sw[2]+sw[3];
        float lp=d_tgt[r]-(logf(S)+Mf);
        float wg=(r<128)?1.0f:(1.0f/16.0f);
        atomicAdd(&d_acc,lp*wg);
        __threadfence();
        int done=atomicAdd(&d_cnt,1);
        if(done==RTOT-1){
            float accv=atomicAdd(&d_acc,0.0f);
            float klv=atomicAdd(&d_kl,0.0f);
            out[0]=-klv+accv;
        }
    }
}

extern "C" void kernel_launch(void* const* d_in, const int* in_sizes, int n_in,
                              void* d_out, int out_size){
    const int*   wl1=(const int*)d_in[0];
    const int*   wl2=(const int*)d_in[1];
    const float* emb=(const float*)d_in[2];
    const float* Wihf=(const float*)d_in[3];
    const float* Whhf=(const float*)d_in[4];
    const float* bihf=(const float*)d_in[5];
    const float* bhhf=(const float*)d_in[6];
    const float* Wihb=(const float*)d_in[7];
    const float* Whhb=(const float*)d_in[8];
    const float* bihb=(const float*)d_in[9];
    const float* bhhb=(const float*)d_in[10];
    const float* UW=(const float*)d_in[11];
    const float* Ub=(const float*)d_in[12];
    const float* SW=(const float*)d_in[13];
    const float* Sb=(const float*)d_in[14];
    const float* fW=(const float*)d_in[15];
    const float* fb=(const float*)d_in[16];
    const float* gW=(const float*)d_in[17];
    const float* gb=(const float*)d_in[18];
    cudaFuncSetAttribute(k_mma, cudaFuncAttributeMaxDynamicSharedMemorySize, SM_TOT);
    k_init<<<256,128>>>(wl1,emb);
    k_xg<<<dim3(128,2),128>>>(Wihf,bihf,bhhf,Wihb,bihb,bhhb);
    k_lstm<<<64+CVB,512>>>(Whhf,Whhb,fW,gW);
    k_us<<<dim3(64,2),256>>>(UW,Ub,SW,Sb);
    k_sample<<<RTOT,512>>>();
    k_mma<<<dim3(NCT,17),256,SM_TOT>>>(fb,gb,wl1,wl2);
    k_final<<<RTOT,128>>>((float*)d_out);
}